// round 2
// baseline (speedup 1.0000x reference)
#include <cuda_runtime.h>

#define NN 100000
#define EE 1600000
#define BB 64
#define EPS_MSG 1e-7f
#define ENC_NEGINF 0x007FFFFFu

// ---------------- scratch (static __device__, no allocations) ----------------
__device__ float g_h[NN * 64];        // node state h
__device__ float g_out64[NN * 64];    // agg + residual (GEMM1 input)
__device__ float g_hidden[NN * 128];  // MLP hidden (also reused as [N,12] for layer 0)
__device__ int   g_deg[NN];
__device__ int   g_tmp[NN];
__device__ int   g_rowptr[NN + 1];
__device__ int   g_pos[NN];
__device__ int   g_col[EE];
__device__ int   g_bsum[128];
__device__ int   g_bscan[128];
__device__ float g_psum[2048 * 128];
__device__ float g_psumsq[2048 * 128];
__device__ float g_scale[128];
__device__ float g_shift[128];
__device__ unsigned g_pool[BB * 64];

// ---------------- helpers ----------------
__device__ __forceinline__ unsigned encf(float f) {
    unsigned u = __float_as_uint(f);
    return (u & 0x80000000u) ? ~u : (u | 0x80000000u);
}
__device__ __forceinline__ float decf(unsigned u) {
    return __uint_as_float((u & 0x80000000u) ? (u ^ 0x80000000u) : ~u);
}

// online softmax accumulate: v is the new message value
#define ONLINE_UPD(v, m, p, q)                       \
    do {                                             \
        if ((v) <= (m)) {                            \
            float _e = __expf((v) - (m));            \
            (p) += _e;                               \
            (q) = fmaf((v), _e, (q));                \
        } else {                                     \
            float _s = __expf((m) - (v));            \
            (p) = fmaf((p), _s, 1.f);                \
            (q) = fmaf((q), _s, (v));                \
            (m) = (v);                               \
        }                                            \
    } while (0)

// ---------------- init ----------------
__global__ void k_init() {
    int i = blockIdx.x * blockDim.x + threadIdx.x;
    if (i < NN) g_deg[i] = 0;
    if (i < BB * 64) g_pool[i] = ENC_NEGINF;
}

// ---------------- CSR build ----------------
__global__ void k_deg(const int* __restrict__ dst) {
    int e = blockIdx.x * blockDim.x + threadIdx.x;
    if (e < EE) atomicAdd(&g_deg[dst[e]], 1);
}

__global__ void __launch_bounds__(1024) k_scan1() {
    __shared__ int s[1024];
    int t = threadIdx.x;
    int idx = blockIdx.x * 1024 + t;
    int v = (idx < NN) ? g_deg[idx] : 0;
    s[t] = v;
    __syncthreads();
    for (int off = 1; off < 1024; off <<= 1) {
        int a = (t >= off) ? s[t - off] : 0;
        __syncthreads();
        s[t] += a;
        __syncthreads();
    }
    if (idx < NN) g_tmp[idx] = s[t];
    if (t == 1023) g_bsum[blockIdx.x] = s[1023];
}

__global__ void k_scan2() {
    __shared__ int s[128];
    int t = threadIdx.x;
    int v = (t < 98) ? g_bsum[t] : 0;
    s[t] = v;
    __syncthreads();
    for (int off = 1; off < 128; off <<= 1) {
        int a = (t >= off) ? s[t - off] : 0;
        __syncthreads();
        s[t] += a;
        __syncthreads();
    }
    g_bscan[t] = s[t];
}

__global__ void k_scan3() {
    int idx = blockIdx.x * blockDim.x + threadIdx.x;
    if (idx >= NN) return;
    int b = idx >> 10;
    int off = (b > 0) ? g_bscan[b - 1] : 0;
    int incl = g_tmp[idx] + off;
    g_rowptr[idx + 1] = incl;
    g_pos[idx] = incl - g_deg[idx];
    if (idx == 0) g_rowptr[0] = 0;
}

__global__ void k_scatter(const int* __restrict__ src, const int* __restrict__ dst) {
    int e = blockIdx.x * blockDim.x + threadIdx.x;
    if (e >= EE) return;
    int p = atomicAdd(&g_pos[dst[e]], 1);
    g_col[p] = src[e];
}

// ---------------- layer 0: fused agg(F=6) + MLP1 (6->12) + BN partials ----------------
__global__ void __launch_bounds__(256) k_l0(const float* __restrict__ x,
                                            const float* __restrict__ w1,
                                            const float* __restrict__ b1) {
    __shared__ float w_s[72];
    __shared__ float sacc[12], sacc2[12];
    int t = threadIdx.x;
    if (t < 72) w_s[t] = w1[t];
    if (t < 12) { sacc[t] = 0.f; sacc2[t] = 0.f; }
    __syncthreads();

    int n = blockIdx.x * 256 + t;
    float hid[12];
#pragma unroll
    for (int j = 0; j < 12; j++) hid[j] = 0.f;

    if (n < NN) {
        int beg = g_rowptr[n], end = g_rowptr[n + 1];
        float m[6], p[6], q[6];
#pragma unroll
        for (int c = 0; c < 6; c++) { m[c] = 0.f; p[c] = 0.f; q[c] = 0.f; }
        for (int e = beg; e < end; e++) {
            int s = g_col[e];
#pragma unroll
            for (int c = 0; c < 6; c++) {
                float v = fmaxf(x[s * 6 + c], 0.f) + EPS_MSG;
                ONLINE_UPD(v, m[c], p[c], q[c]);
            }
        }
        float o[6];
#pragma unroll
        for (int c = 0; c < 6; c++) o[c] = q[c] / (p[c] + 1e-16f) + x[n * 6 + c];
#pragma unroll
        for (int j = 0; j < 12; j++) {
            float a = b1[j];
#pragma unroll
            for (int c = 0; c < 6; c++) a = fmaf(o[c], w_s[c * 12 + j], a);
            hid[j] = a;
            g_hidden[n * 12 + j] = a;
        }
    }
    // block-level BN partials (warp shuffle reduce -> smem atomics -> slot)
#pragma unroll
    for (int j = 0; j < 12; j++) {
        float v = hid[j], v2 = v * v;
        for (int off = 16; off; off >>= 1) {
            v += __shfl_down_sync(0xffffffffu, v, off);
            v2 += __shfl_down_sync(0xffffffffu, v2, off);
        }
        if ((t & 31) == 0) { atomicAdd(&sacc[j], v); atomicAdd(&sacc2[j], v2); }
    }
    __syncthreads();
    if (t < 12) {
        g_psum[blockIdx.x * 12 + t] = sacc[t];
        g_psumsq[blockIdx.x * 12 + t] = sacc2[t];
    }
}

// ---------------- BN finalize (shared) ----------------
__global__ void k_bnfin(const float* __restrict__ gam, const float* __restrict__ bet,
                        int C, int nb) {
    int c = threadIdx.x;
    if (c >= C) return;
    float s = 0.f, s2 = 0.f;
#pragma unroll 4
    for (int i = 0; i < nb; i++) { s += g_psum[i * C + c]; s2 += g_psumsq[i * C + c]; }
    float mu = s / (float)NN;
    float var = fmaxf(s2 / (float)NN - mu * mu, 0.f);
    float sc = gam[c] * rsqrtf(var + 1e-5f);
    g_scale[c] = sc;
    g_shift[c] = bet[c] - mu * sc;
}

// ---------------- layer 0 MLP2: relu(bn(hid12)) @ w2[12,64] + b2 -> h = relu(.) ----------------
__global__ void __launch_bounds__(256) k_l0_mlp2(const float* __restrict__ w2,
                                                 const float* __restrict__ b2) {
    __shared__ float w_s[12 * 64];
    __shared__ float b_s[64];
    int t = threadIdx.x;
    for (int i = t; i < 768; i += 256) w_s[i] = w2[i];
    if (t < 64) b_s[t] = b2[t];
    __syncthreads();
    int n = blockIdx.x * 256 + t;
    if (n >= NN) return;
    float v[12];
#pragma unroll
    for (int j = 0; j < 12; j++)
        v[j] = fmaxf(fmaf(g_hidden[n * 12 + j], g_scale[j], g_shift[j]), 0.f);
    for (int c0 = 0; c0 < 64; c0 += 4) {
        float a0 = b_s[c0], a1 = b_s[c0 + 1], a2 = b_s[c0 + 2], a3 = b_s[c0 + 3];
#pragma unroll
        for (int j = 0; j < 12; j++) {
            float vj = v[j];
            a0 = fmaf(vj, w_s[j * 64 + c0], a0);
            a1 = fmaf(vj, w_s[j * 64 + c0 + 1], a1);
            a2 = fmaf(vj, w_s[j * 64 + c0 + 2], a2);
            a3 = fmaf(vj, w_s[j * 64 + c0 + 3], a3);
        }
        float4 o;
        o.x = fmaxf(a0, 0.f); o.y = fmaxf(a1, 0.f);
        o.z = fmaxf(a2, 0.f); o.w = fmaxf(a3, 0.f);
        *(float4*)(g_h + n * 64 + c0) = o;
    }
}

// ---------------- aggregation, F=64: warp/node, single-pass online softmax ----------------
__global__ void __launch_bounds__(256) k_agg64() {
    int gt = blockIdx.x * blockDim.x + threadIdx.x;
    int n = gt >> 5;
    if (n >= NN) return;
    int l = gt & 31;
    int beg = g_rowptr[n], end = g_rowptr[n + 1];

    float m0 = 0.f, p0 = 0.f, q0 = 0.f;
    float m1 = 0.f, p1 = 0.f, q1 = 0.f;
    int e = beg;
    for (; e + 4 <= end; e += 4) {
        int i0 = g_col[e], i1 = g_col[e + 1], i2 = g_col[e + 2], i3 = g_col[e + 3];
        float a0 = g_h[i0 * 64 + l], b0 = g_h[i0 * 64 + 32 + l];
        float a1 = g_h[i1 * 64 + l], b1 = g_h[i1 * 64 + 32 + l];
        float a2 = g_h[i2 * 64 + l], b2 = g_h[i2 * 64 + 32 + l];
        float a3 = g_h[i3 * 64 + l], b3 = g_h[i3 * 64 + 32 + l];
        a0 = fmaxf(a0, 0.f) + EPS_MSG; b0 = fmaxf(b0, 0.f) + EPS_MSG;
        a1 = fmaxf(a1, 0.f) + EPS_MSG; b1 = fmaxf(b1, 0.f) + EPS_MSG;
        a2 = fmaxf(a2, 0.f) + EPS_MSG; b2 = fmaxf(b2, 0.f) + EPS_MSG;
        a3 = fmaxf(a3, 0.f) + EPS_MSG; b3 = fmaxf(b3, 0.f) + EPS_MSG;
        ONLINE_UPD(a0, m0, p0, q0); ONLINE_UPD(b0, m1, p1, q1);
        ONLINE_UPD(a1, m0, p0, q0); ONLINE_UPD(b1, m1, p1, q1);
        ONLINE_UPD(a2, m0, p0, q0); ONLINE_UPD(b2, m1, p1, q1);
        ONLINE_UPD(a3, m0, p0, q0); ONLINE_UPD(b3, m1, p1, q1);
    }
    for (; e < end; e++) {
        int i0 = g_col[e];
        float a0 = fmaxf(g_h[i0 * 64 + l], 0.f) + EPS_MSG;
        float b0 = fmaxf(g_h[i0 * 64 + 32 + l], 0.f) + EPS_MSG;
        ONLINE_UPD(a0, m0, p0, q0);
        ONLINE_UPD(b0, m1, p1, q1);
    }

    float r0 = fmaxf(g_h[n * 64 + l], 0.f);
    float r1 = fmaxf(g_h[n * 64 + 32 + l], 0.f);
    g_out64[n * 64 + l]      = q0 / (p0 + 1e-16f) + r0;
    g_out64[n * 64 + 32 + l] = q1 / (p1 + 1e-16f) + r1;
}

// ---------------- GEMM1: g_out64[N,64] @ W[64,128] + b -> g_hidden[N,128] ----------------
// Fused: per-block BN partial stats of (acc + bias) into g_psum/g_psumsq.
__global__ void __launch_bounds__(256) k_gemm1(const float* __restrict__ W,
                                               const float* __restrict__ bias) {
    __shared__ float w_s[32 * 128];
    __shared__ float a_s[32 * 68];
    int t = threadIdx.x;
    int row0 = blockIdx.x * 64;
    float acc[8][4];
#pragma unroll
    for (int i = 0; i < 8; i++)
#pragma unroll
        for (int j = 0; j < 4; j++) acc[i][j] = 0.f;
    int tc = t & 31, tr = t >> 5;
    int c4 = tc * 4, r0 = tr * 8;

    for (int kc = 0; kc < 64; kc += 32) {
#pragma unroll
        for (int i = t; i < 1024; i += 256)
            ((float4*)w_s)[i] = ((const float4*)(W + kc * 128))[i];
#pragma unroll
        for (int i = t; i < 512; i += 256) {
            int r = i >> 3, kk = (i & 7) << 2;
            int row = row0 + r;
            float4 v = make_float4(0.f, 0.f, 0.f, 0.f);
            if (row < NN) v = *(const float4*)(g_out64 + row * 64 + kc + kk);
            a_s[(kk + 0) * 68 + r] = v.x;
            a_s[(kk + 1) * 68 + r] = v.y;
            a_s[(kk + 2) * 68 + r] = v.z;
            a_s[(kk + 3) * 68 + r] = v.w;
        }
        __syncthreads();
#pragma unroll
        for (int k = 0; k < 32; k++) {
            float4 wv = *(float4*)(w_s + k * 128 + c4);
            float4 aA = *(float4*)(a_s + k * 68 + r0);
            float4 aB = *(float4*)(a_s + k * 68 + r0 + 4);
            float ar[8] = {aA.x, aA.y, aA.z, aA.w, aB.x, aB.y, aB.z, aB.w};
            float wr[4] = {wv.x, wv.y, wv.z, wv.w};
#pragma unroll
            for (int ii = 0; ii < 8; ii++)
#pragma unroll
                for (int jj = 0; jj < 4; jj++)
                    acc[ii][jj] = fmaf(ar[ii], wr[jj], acc[ii][jj]);
        }
        __syncthreads();
    }
    float4 bv = *(const float4*)(bias + c4);
    float bb[4] = {bv.x, bv.y, bv.z, bv.w};
#pragma unroll
    for (int ii = 0; ii < 8; ii++) {
        int row = row0 + r0 + ii;
        if (row < NN) {
            float4 o;
            o.x = acc[ii][0] + bb[0]; o.y = acc[ii][1] + bb[1];
            o.z = acc[ii][2] + bb[2]; o.w = acc[ii][3] + bb[3];
            *(float4*)(g_hidden + row * 128 + c4) = o;
        }
    }
    // fused BN partial stats: reduce over this block's 64 rows per column
    float* red  = w_s;          // [8][128]
    float* red2 = w_s + 1024;   // [8][128]
#pragma unroll
    for (int jj = 0; jj < 4; jj++) {
        float s = 0.f, s2 = 0.f;
#pragma unroll
        for (int ii = 0; ii < 8; ii++) {
            int row = row0 + r0 + ii;
            if (row < NN) {
                float v = acc[ii][jj] + bb[jj];
                s += v;
                s2 = fmaf(v, v, s2);
            }
        }
        red[tr * 128 + c4 + jj]  = s;
        red2[tr * 128 + c4 + jj] = s2;
    }
    __syncthreads();
    if (t < 128) {
        float s = 0.f, s2 = 0.f;
#pragma unroll
        for (int i = 0; i < 8; i++) {
            s += red[i * 128 + t];
            s2 += red2[i * 128 + t];
        }
        g_psum[blockIdx.x * 128 + t]   = s;
        g_psumsq[blockIdx.x * 128 + t] = s2;
    }
}

// ---------------- GEMM2: relu(bn(g_hidden))[N,128] @ W[128,64] + b, h += . ----------------
__global__ void __launch_bounds__(256) k_gemm2(const float* __restrict__ W,
                                               const float* __restrict__ bias) {
    __shared__ float w_s[32 * 64];
    __shared__ float a_s[32 * 68];
    int t = threadIdx.x;
    int row0 = blockIdx.x * 64;
    float acc[8][2];
#pragma unroll
    for (int i = 0; i < 8; i++) { acc[i][0] = 0.f; acc[i][1] = 0.f; }
    int tc = t & 31, tr = t >> 5;
    int c2 = tc * 2, r0 = tr * 8;

    for (int kc = 0; kc < 128; kc += 32) {
#pragma unroll
        for (int i = t; i < 512; i += 256)
            ((float4*)w_s)[i] = ((const float4*)(W + kc * 64))[i];
#pragma unroll
        for (int i = t; i < 512; i += 256) {
            int r = i >> 3, kk = (i & 7) << 2;
            int row = row0 + r;
            float4 v = make_float4(0.f, 0.f, 0.f, 0.f);
            if (row < NN) {
                float4 hv = *(const float4*)(g_hidden + row * 128 + kc + kk);
                float4 sc = *(const float4*)(g_scale + kc + kk);
                float4 sh = *(const float4*)(g_shift + kc + kk);
                v.x = fmaxf(fmaf(hv.x, sc.x, sh.x), 0.f);
                v.y = fmaxf(fmaf(hv.y, sc.y, sh.y), 0.f);
                v.z = fmaxf(fmaf(hv.z, sc.z, sh.z), 0.f);
                v.w = fmaxf(fmaf(hv.w, sc.w, sh.w), 0.f);
            }
            a_s[(kk + 0) * 68 + r] = v.x;
            a_s[(kk + 1) * 68 + r] = v.y;
            a_s[(kk + 2) * 68 + r] = v.z;
            a_s[(kk + 3) * 68 + r] = v.w;
        }
        __syncthreads();
#pragma unroll
        for (int k = 0; k < 32; k++) {
            float2 wv = *(float2*)(w_s + k * 64 + c2);
            float4 aA = *(float4*)(a_s + k * 68 + r0);
            float4 aB = *(float4*)(a_s + k * 68 + r0 + 4);
            float ar[8] = {aA.x, aA.y, aA.z, aA.w, aB.x, aB.y, aB.z, aB.w};
#pragma unroll
            for (int ii = 0; ii < 8; ii++) {
                acc[ii][0] = fmaf(ar[ii], wv.x, acc[ii][0]);
                acc[ii][1] = fmaf(ar[ii], wv.y, acc[ii][1]);
            }
        }
        __syncthreads();
    }
    float b0 = bias[c2], b1v = bias[c2 + 1];
#pragma unroll
    for (int ii = 0; ii < 8; ii++) {
        int row = row0 + r0 + ii;
        if (row < NN) {
            float2 hv = *(float2*)(g_h + row * 64 + c2);
            hv.x += acc[ii][0] + b0;
            hv.y += acc[ii][1] + b1v;
            *(float2*)(g_h + row * 64 + c2) = hv;
        }
    }
}

// ---------------- pool: run-length max over sorted batch + encoded atomicMax ----------------
__global__ void __launch_bounds__(256) k_pool(const int* __restrict__ batch) {
    int t = threadIdx.x;
    int c = t & 63, sub = t >> 6;
    int n0 = blockIdx.x * 64 + sub * 16;
    float cur = -__int_as_float(0x7f800000);  // -inf
    int curb = -1;
    for (int i = 0; i < 16; i++) {
        int n = n0 + i;
        if (n >= NN) break;
        int b = batch[n];
        if (b != curb) {
            if (curb >= 0) atomicMax(&g_pool[curb * 64 + c], encf(cur));
            curb = b;
            cur = -__int_as_float(0x7f800000);
        }
        cur = fmaxf(cur, g_h[n * 64 + c]);
    }
    if (curb >= 0) atomicMax(&g_pool[curb * 64 + c], encf(cur));
}

// ---------------- final MLP: [64,64] -> relu -> [64,80] ----------------
__global__ void __launch_bounds__(256) k_final(const float* __restrict__ w1,
                                               const float* __restrict__ b1,
                                               const float* __restrict__ w2,
                                               const float* __restrict__ b2,
                                               float* __restrict__ out) {
    __shared__ float g_s[64 * 64];
    __shared__ float t_s[64 * 64];
    int t = threadIdx.x;
    for (int i = t; i < 4096; i += 256) {
        unsigned u = g_pool[i];
        g_s[i] = (u == ENC_NEGINF) ? 0.f : decf(u);
    }
    __syncthreads();
    for (int e = t; e < 4096; e += 256) {
        int r = e >> 6, c = e & 63;
        float a = b1[c];
        for (int k = 0; k < 64; k++) a = fmaf(g_s[r * 64 + k], w1[k * 64 + c], a);
        t_s[e] = fmaxf(a, 0.f);
    }
    __syncthreads();
    for (int e = t; e < 5120; e += 256) {
        int r = e / 80, c = e % 80;
        float a = b2[c];
        for (int k = 0; k < 64; k++) a = fmaf(t_s[r * 64 + k], w2[k * 80 + c], a);
        out[e] = a;
    }
}

// ---------------- launch ----------------
extern "C" void kernel_launch(void* const* d_in, const int* in_sizes, int n_in,
                              void* d_out, int out_size) {
    const float* x    = (const float*)d_in[0];
    const int*   ei   = (const int*)d_in[1];
    const int*   batch = (const int*)d_in[2];
    const float* cw1  = (const float*)d_in[3];
    const float* cb1  = (const float*)d_in[4];
    const float* cg1  = (const float*)d_in[5];
    const float* cbe1 = (const float*)d_in[6];
    const float* cw2  = (const float*)d_in[7];
    const float* cb2  = (const float*)d_in[8];
    const float* Lw1  = (const float*)d_in[9];
    const float* Lb1  = (const float*)d_in[10];
    const float* Lg1  = (const float*)d_in[11];
    const float* Lbe1 = (const float*)d_in[12];
    const float* Lw2  = (const float*)d_in[13];
    const float* Lb2  = (const float*)d_in[14];
    const float* mw1  = (const float*)d_in[15];
    const float* mb1  = (const float*)d_in[16];
    const float* mw2  = (const float*)d_in[17];
    const float* mb2  = (const float*)d_in[18];
    float* out = (float*)d_out;

    const int* src = ei;
    const int* dst = ei + EE;

    // CSR build
    k_init<<<391, 256>>>();
    k_deg<<<EE / 256, 256>>>(dst);
    k_scan1<<<98, 1024>>>();
    k_scan2<<<1, 128>>>();
    k_scan3<<<391, 256>>>();
    k_scatter<<<EE / 256, 256>>>(src, dst);

    // layer 0 (6 -> 12 -> 64), h = relu(genconv(x))
    k_l0<<<391, 256>>>(x, cw1, cb1);
    k_bnfin<<<1, 32>>>(cg1, cbe1, 12, 391);
    k_l0_mlp2<<<391, 256>>>(cw2, cb2);

    // layers 1..3: h += genconv(relu(h))
    for (int i = 0; i < 3; i++) {
        k_agg64<<<12500, 256>>>();
        k_gemm1<<<1563, 256>>>(Lw1 + i * 64 * 128, Lb1 + i * 128);
        k_bnfin<<<1, 128>>>(Lg1 + i * 128, Lbe1 + i * 128, 128, 1563);
        k_gemm2<<<1563, 256>>>(Lw2 + i * 128 * 64, Lb2 + i * 64);
    }

    k_pool<<<1563, 256>>>(batch);
    k_final<<<1, 256>>>(mw1, mb1, mw2, mb2, out);
}

// round 3
// speedup vs baseline: 1.3033x; 1.3033x over previous
#include <cuda_runtime.h>

#define NN 100000
#define EE 1600000
#define BB 64
#define EPS_MSG 1e-7f
#define ENC_NEGINF 0x007FFFFFu

// ---------------- scratch (static __device__, no allocations) ----------------
__device__ float g_h[NN * 64];        // node state h
__device__ float g_out64[NN * 64];    // agg + residual (GEMM1 input)
__device__ float g_hidden[NN * 128];  // MLP hidden (also reused as [N,12] for layer 0)
__device__ int   g_deg[NN];
__device__ int   g_tmp[NN];
__device__ int   g_rowptr[NN + 1];
__device__ int   g_pos[NN];
__device__ int   g_col[EE];
__device__ int   g_bsum[128];
__device__ int   g_bscan[128];
__device__ float g_psum[2048 * 128];
__device__ float g_psumsq[2048 * 128];
__device__ float g_scale[128];
__device__ float g_shift[128];
__device__ unsigned g_pool[BB * 64];

// ---------------- helpers ----------------
__device__ __forceinline__ unsigned encf(float f) {
    unsigned u = __float_as_uint(f);
    return (u & 0x80000000u) ? ~u : (u | 0x80000000u);
}
__device__ __forceinline__ float decf(unsigned u) {
    return __uint_as_float((u & 0x80000000u) ? (u ^ 0x80000000u) : ~u);
}
__device__ __forceinline__ float f2tf(float x) {
    unsigned r;
    asm("cvt.rna.tf32.f32 %0, %1;" : "=r"(r) : "f"(x));
    return __uint_as_float(r);
}
__device__ __forceinline__ void mma_tf32(float* d, unsigned a0, unsigned a1,
                                         unsigned a2, unsigned a3,
                                         unsigned b0, unsigned b1) {
    asm volatile(
        "mma.sync.aligned.m16n8k8.row.col.f32.tf32.tf32.f32 "
        "{%0,%1,%2,%3}, {%4,%5,%6,%7}, {%8,%9}, {%0,%1,%2,%3};"
        : "+f"(d[0]), "+f"(d[1]), "+f"(d[2]), "+f"(d[3])
        : "r"(a0), "r"(a1), "r"(a2), "r"(a3), "r"(b0), "r"(b1));
}

// online softmax accumulate: v is the new message value
#define ONLINE_UPD(v, m, p, q)                       \
    do {                                             \
        if ((v) <= (m)) {                            \
            float _e = __expf((v) - (m));            \
            (p) += _e;                               \
            (q) = fmaf((v), _e, (q));                \
        } else {                                     \
            float _s = __expf((m) - (v));            \
            (p) = fmaf((p), _s, 1.f);                \
            (q) = fmaf((q), _s, (v));                \
            (m) = (v);                               \
        }                                            \
    } while (0)

// ---------------- init ----------------
__global__ void k_init() {
    int i = blockIdx.x * blockDim.x + threadIdx.x;
    if (i < NN) g_deg[i] = 0;
    if (i < BB * 64) g_pool[i] = ENC_NEGINF;
}

// ---------------- CSR build ----------------
__global__ void k_deg(const int* __restrict__ dst) {
    int e = blockIdx.x * blockDim.x + threadIdx.x;
    if (e < EE) atomicAdd(&g_deg[dst[e]], 1);
}

__global__ void __launch_bounds__(1024) k_scan1() {
    __shared__ int s[1024];
    int t = threadIdx.x;
    int idx = blockIdx.x * 1024 + t;
    int v = (idx < NN) ? g_deg[idx] : 0;
    s[t] = v;
    __syncthreads();
    for (int off = 1; off < 1024; off <<= 1) {
        int a = (t >= off) ? s[t - off] : 0;
        __syncthreads();
        s[t] += a;
        __syncthreads();
    }
    if (idx < NN) g_tmp[idx] = s[t];
    if (t == 1023) g_bsum[blockIdx.x] = s[1023];
}

__global__ void k_scan2() {
    __shared__ int s[128];
    int t = threadIdx.x;
    int v = (t < 98) ? g_bsum[t] : 0;
    s[t] = v;
    __syncthreads();
    for (int off = 1; off < 128; off <<= 1) {
        int a = (t >= off) ? s[t - off] : 0;
        __syncthreads();
        s[t] += a;
        __syncthreads();
    }
    g_bscan[t] = s[t];
}

__global__ void k_scan3() {
    int idx = blockIdx.x * blockDim.x + threadIdx.x;
    if (idx >= NN) return;
    int b = idx >> 10;
    int off = (b > 0) ? g_bscan[b - 1] : 0;
    int incl = g_tmp[idx] + off;
    g_rowptr[idx + 1] = incl;
    g_pos[idx] = incl - g_deg[idx];
    if (idx == 0) g_rowptr[0] = 0;
}

__global__ void k_scatter(const int* __restrict__ src, const int* __restrict__ dst) {
    int e = blockIdx.x * blockDim.x + threadIdx.x;
    if (e >= EE) return;
    int p = atomicAdd(&g_pos[dst[e]], 1);
    g_col[p] = src[e];
}

// ---------------- layer 0: fused agg(F=6) + MLP1 (6->12) + BN partials ----------------
__global__ void __launch_bounds__(256) k_l0(const float* __restrict__ x,
                                            const float* __restrict__ w1,
                                            const float* __restrict__ b1) {
    __shared__ float w_s[72];
    __shared__ float sacc[12], sacc2[12];
    int t = threadIdx.x;
    if (t < 72) w_s[t] = w1[t];
    if (t < 12) { sacc[t] = 0.f; sacc2[t] = 0.f; }
    __syncthreads();

    int n = blockIdx.x * 256 + t;
    float hid[12];
#pragma unroll
    for (int j = 0; j < 12; j++) hid[j] = 0.f;

    if (n < NN) {
        int beg = g_rowptr[n], end = g_rowptr[n + 1];
        float m[6], p[6], q[6];
#pragma unroll
        for (int c = 0; c < 6; c++) { m[c] = 0.f; p[c] = 0.f; q[c] = 0.f; }
        for (int e = beg; e < end; e++) {
            int s = g_col[e];
#pragma unroll
            for (int c = 0; c < 6; c++) {
                float v = fmaxf(x[s * 6 + c], 0.f) + EPS_MSG;
                ONLINE_UPD(v, m[c], p[c], q[c]);
            }
        }
        float o[6];
#pragma unroll
        for (int c = 0; c < 6; c++) o[c] = q[c] / (p[c] + 1e-16f) + x[n * 6 + c];
#pragma unroll
        for (int j = 0; j < 12; j++) {
            float a = b1[j];
#pragma unroll
            for (int c = 0; c < 6; c++) a = fmaf(o[c], w_s[c * 12 + j], a);
            hid[j] = a;
            g_hidden[n * 12 + j] = a;
        }
    }
#pragma unroll
    for (int j = 0; j < 12; j++) {
        float v = hid[j], v2 = v * v;
        for (int off = 16; off; off >>= 1) {
            v += __shfl_down_sync(0xffffffffu, v, off);
            v2 += __shfl_down_sync(0xffffffffu, v2, off);
        }
        if ((t & 31) == 0) { atomicAdd(&sacc[j], v); atomicAdd(&sacc2[j], v2); }
    }
    __syncthreads();
    if (t < 12) {
        g_psum[blockIdx.x * 12 + t] = sacc[t];
        g_psumsq[blockIdx.x * 12 + t] = sacc2[t];
    }
}

// ---------------- BN finalize (shared) ----------------
__global__ void k_bnfin(const float* __restrict__ gam, const float* __restrict__ bet,
                        int C, int nb) {
    int c = threadIdx.x;
    if (c >= C) return;
    float s = 0.f, s2 = 0.f;
#pragma unroll 4
    for (int i = 0; i < nb; i++) { s += g_psum[i * C + c]; s2 += g_psumsq[i * C + c]; }
    float mu = s / (float)NN;
    float var = fmaxf(s2 / (float)NN - mu * mu, 0.f);
    float sc = gam[c] * rsqrtf(var + 1e-5f);
    g_scale[c] = sc;
    g_shift[c] = bet[c] - mu * sc;
}

// ---------------- layer 0 MLP2: relu(bn(hid12)) @ w2[12,64] + b2 -> h = relu(.) ----------------
__global__ void __launch_bounds__(256) k_l0_mlp2(const float* __restrict__ w2,
                                                 const float* __restrict__ b2) {
    __shared__ float w_s[12 * 64];
    __shared__ float b_s[64];
    int t = threadIdx.x;
    for (int i = t; i < 768; i += 256) w_s[i] = w2[i];
    if (t < 64) b_s[t] = b2[t];
    __syncthreads();
    int n = blockIdx.x * 256 + t;
    if (n >= NN) return;
    float v[12];
#pragma unroll
    for (int j = 0; j < 12; j++)
        v[j] = fmaxf(fmaf(g_hidden[n * 12 + j], g_scale[j], g_shift[j]), 0.f);
    for (int c0 = 0; c0 < 64; c0 += 4) {
        float a0 = b_s[c0], a1 = b_s[c0 + 1], a2 = b_s[c0 + 2], a3 = b_s[c0 + 3];
#pragma unroll
        for (int j = 0; j < 12; j++) {
            float vj = v[j];
            a0 = fmaf(vj, w_s[j * 64 + c0], a0);
            a1 = fmaf(vj, w_s[j * 64 + c0 + 1], a1);
            a2 = fmaf(vj, w_s[j * 64 + c0 + 2], a2);
            a3 = fmaf(vj, w_s[j * 64 + c0 + 3], a3);
        }
        float4 o;
        o.x = fmaxf(a0, 0.f); o.y = fmaxf(a1, 0.f);
        o.z = fmaxf(a2, 0.f); o.w = fmaxf(a3, 0.f);
        *(float4*)(g_h + n * 64 + c0) = o;
    }
}

// ---------------- aggregation, F=64: warp/node, single-pass online softmax ----------------
__global__ void __launch_bounds__(256) k_agg64() {
    int gt = blockIdx.x * blockDim.x + threadIdx.x;
    int n = gt >> 5;
    if (n >= NN) return;
    int l = gt & 31;
    int beg = g_rowptr[n], end = g_rowptr[n + 1];

    float m0 = 0.f, p0 = 0.f, q0 = 0.f;
    float m1 = 0.f, p1 = 0.f, q1 = 0.f;
    int e = beg;
    for (; e + 4 <= end; e += 4) {
        int i0 = g_col[e], i1 = g_col[e + 1], i2 = g_col[e + 2], i3 = g_col[e + 3];
        float a0 = g_h[i0 * 64 + l], b0 = g_h[i0 * 64 + 32 + l];
        float a1 = g_h[i1 * 64 + l], b1 = g_h[i1 * 64 + 32 + l];
        float a2 = g_h[i2 * 64 + l], b2 = g_h[i2 * 64 + 32 + l];
        float a3 = g_h[i3 * 64 + l], b3 = g_h[i3 * 64 + 32 + l];
        a0 = fmaxf(a0, 0.f) + EPS_MSG; b0 = fmaxf(b0, 0.f) + EPS_MSG;
        a1 = fmaxf(a1, 0.f) + EPS_MSG; b1 = fmaxf(b1, 0.f) + EPS_MSG;
        a2 = fmaxf(a2, 0.f) + EPS_MSG; b2 = fmaxf(b2, 0.f) + EPS_MSG;
        a3 = fmaxf(a3, 0.f) + EPS_MSG; b3 = fmaxf(b3, 0.f) + EPS_MSG;
        ONLINE_UPD(a0, m0, p0, q0); ONLINE_UPD(b0, m1, p1, q1);
        ONLINE_UPD(a1, m0, p0, q0); ONLINE_UPD(b1, m1, p1, q1);
        ONLINE_UPD(a2, m0, p0, q0); ONLINE_UPD(b2, m1, p1, q1);
        ONLINE_UPD(a3, m0, p0, q0); ONLINE_UPD(b3, m1, p1, q1);
    }
    for (; e < end; e++) {
        int i0 = g_col[e];
        float a0 = fmaxf(g_h[i0 * 64 + l], 0.f) + EPS_MSG;
        float b0 = fmaxf(g_h[i0 * 64 + 32 + l], 0.f) + EPS_MSG;
        ONLINE_UPD(a0, m0, p0, q0);
        ONLINE_UPD(b0, m1, p1, q1);
    }

    float r0 = fmaxf(g_h[n * 64 + l], 0.f);
    float r1 = fmaxf(g_h[n * 64 + 32 + l], 0.f);
    g_out64[n * 64 + l]      = q0 / (p0 + 1e-16f) + r0;
    g_out64[n * 64 + 32 + l] = q1 / (p1 + 1e-16f) + r1;
}

// ---------------- GEMM1 (tf32 mma): g_out64[N,64] @ W[64,128] + b -> g_hidden[N,128]
// block: 128 rows x 128 cols, K chunked by 32. 8 warps; warp w owns cols [16w,16w+16).
// Fused BN partial stats into g_psum/g_psumsq[bid*128 + col].
__global__ void __launch_bounds__(256) k_gemm1(const float* __restrict__ W,
                                               const float* __restrict__ bias) {
    __shared__ float a_s[128 * 36];   // [row][k] stride 36
    __shared__ float w_s[32 * 132];   // [k][n] stride 132
    int t = threadIdx.x, lane = t & 31, warp = t >> 5;
    int q = lane & 3, g = lane >> 2;
    int row0 = blockIdx.x * 128;
    int n0w = warp * 16;
    float acc[8][2][4];
#pragma unroll
    for (int i = 0; i < 8; i++)
#pragma unroll
        for (int j = 0; j < 2; j++)
#pragma unroll
            for (int k = 0; k < 4; k++) acc[i][j][k] = 0.f;

    for (int kc = 0; kc < 64; kc += 32) {
        // stage A chunk [128 rows][32 k]
#pragma unroll
        for (int i = t; i < 1024; i += 256) {
            int r = i >> 3, kk = (i & 7) << 2;
            int row = row0 + r;
            float4 v = make_float4(0.f, 0.f, 0.f, 0.f);
            if (row < NN) v = *(const float4*)(g_out64 + row * 64 + kc + kk);
            float4 o;
            o.x = f2tf(v.x); o.y = f2tf(v.y); o.z = f2tf(v.z); o.w = f2tf(v.w);
            *(float4*)(a_s + r * 36 + kk) = o;
        }
        // stage W chunk [32 k][128 n]
#pragma unroll
        for (int i = t; i < 1024; i += 256) {
            int kl = i >> 5, n4 = (i & 31) << 2;
            float4 v = *(const float4*)(W + (kc + kl) * 128 + n4);
            float4 o;
            o.x = f2tf(v.x); o.y = f2tf(v.y); o.z = f2tf(v.z); o.w = f2tf(v.w);
            *(float4*)(w_s + kl * 132 + n4) = o;
        }
        __syncthreads();
#pragma unroll
        for (int kk = 0; kk < 32; kk += 8) {
            unsigned b[2][2];
#pragma unroll
            for (int nt = 0; nt < 2; nt++) {
                int n = n0w + nt * 8 + g;
                b[nt][0] = __float_as_uint(w_s[(kk + q) * 132 + n]);
                b[nt][1] = __float_as_uint(w_s[(kk + 4 + q) * 132 + n]);
            }
#pragma unroll
            for (int mt = 0; mt < 8; mt++) {
                int r = mt * 16 + g;
                unsigned a0 = __float_as_uint(a_s[r * 36 + kk + q]);
                unsigned a1 = __float_as_uint(a_s[(r + 8) * 36 + kk + q]);
                unsigned a2 = __float_as_uint(a_s[r * 36 + kk + 4 + q]);
                unsigned a3 = __float_as_uint(a_s[(r + 8) * 36 + kk + 4 + q]);
                mma_tf32(acc[mt][0], a0, a1, a2, a3, b[0][0], b[0][1]);
                mma_tf32(acc[mt][1], a0, a1, a2, a3, b[1][0], b[1][1]);
            }
        }
        __syncthreads();
    }
    // epilogue: +bias, store, fused BN partial stats
#pragma unroll
    for (int nt = 0; nt < 2; nt++) {
        int c = n0w + nt * 8 + 2 * q;
        float2 bv = *(const float2*)(bias + c);
        float s0 = 0.f, s1 = 0.f, s20 = 0.f, s21 = 0.f;
#pragma unroll
        for (int mt = 0; mt < 8; mt++) {
            int rA = row0 + mt * 16 + g, rB = rA + 8;
            float v0 = acc[mt][nt][0] + bv.x, v1 = acc[mt][nt][1] + bv.y;
            float v2 = acc[mt][nt][2] + bv.x, v3 = acc[mt][nt][3] + bv.y;
            if (rA < NN) {
                *(float2*)(g_hidden + rA * 128 + c) = make_float2(v0, v1);
                s0 += v0; s20 = fmaf(v0, v0, s20);
                s1 += v1; s21 = fmaf(v1, v1, s21);
            }
            if (rB < NN) {
                *(float2*)(g_hidden + rB * 128 + c) = make_float2(v2, v3);
                s0 += v2; s20 = fmaf(v2, v2, s20);
                s1 += v3; s21 = fmaf(v3, v3, s21);
            }
        }
#pragma unroll
        for (int off = 16; off >= 4; off >>= 1) {
            s0 += __shfl_down_sync(0xffffffffu, s0, off);
            s1 += __shfl_down_sync(0xffffffffu, s1, off);
            s20 += __shfl_down_sync(0xffffffffu, s20, off);
            s21 += __shfl_down_sync(0xffffffffu, s21, off);
        }
        if (lane < 4) {
            int cc = n0w + nt * 8 + 2 * lane;
            g_psum[blockIdx.x * 128 + cc] = s0;
            g_psum[blockIdx.x * 128 + cc + 1] = s1;
            g_psumsq[blockIdx.x * 128 + cc] = s20;
            g_psumsq[blockIdx.x * 128 + cc + 1] = s21;
        }
    }
}

// ---------------- GEMM2 (tf32 mma): relu(bn(g_hidden))[N,128] @ W[128,64] + b; h += .
// block: 128 rows x 64 cols, K chunked by 32. 8 warps; warp w owns cols [8w, 8w+8).
__global__ void __launch_bounds__(256) k_gemm2(const float* __restrict__ W,
                                               const float* __restrict__ bias) {
    __shared__ float a_s[128 * 36];   // [row][k] stride 36
    __shared__ float w_s[32 * 68];    // [k][n] stride 68
    int t = threadIdx.x, lane = t & 31, warp = t >> 5;
    int q = lane & 3, g = lane >> 2;
    int row0 = blockIdx.x * 128;
    int n0w = warp * 8;
    float acc[8][4];
#pragma unroll
    for (int i = 0; i < 8; i++)
#pragma unroll
        for (int k = 0; k < 4; k++) acc[i][k] = 0.f;

    for (int kc = 0; kc < 128; kc += 32) {
        // stage A chunk with bn+relu
#pragma unroll
        for (int i = t; i < 1024; i += 256) {
            int r = i >> 3, kk = (i & 7) << 2;
            int row = row0 + r;
            float4 o = make_float4(0.f, 0.f, 0.f, 0.f);
            if (row < NN) {
                float4 hv = *(const float4*)(g_hidden + row * 128 + kc + kk);
                float4 sc = *(const float4*)(g_scale + kc + kk);
                float4 sh = *(const float4*)(g_shift + kc + kk);
                o.x = f2tf(fmaxf(fmaf(hv.x, sc.x, sh.x), 0.f));
                o.y = f2tf(fmaxf(fmaf(hv.y, sc.y, sh.y), 0.f));
                o.z = f2tf(fmaxf(fmaf(hv.z, sc.z, sh.z), 0.f));
                o.w = f2tf(fmaxf(fmaf(hv.w, sc.w, sh.w), 0.f));
            }
            *(float4*)(a_s + r * 36 + kk) = o;
        }
        // stage W chunk [32 k][64 n]
#pragma unroll
        for (int i = t; i < 512; i += 256) {
            int kl = i >> 4, n4 = (i & 15) << 2;
            float4 v = *(const float4*)(W + (kc + kl) * 64 + n4);
            float4 o;
            o.x = f2tf(v.x); o.y = f2tf(v.y); o.z = f2tf(v.z); o.w = f2tf(v.w);
            *(float4*)(w_s + kl * 68 + n4) = o;
        }
        __syncthreads();
#pragma unroll
        for (int kk = 0; kk < 32; kk += 8) {
            int n = n0w + g;
            unsigned b0 = __float_as_uint(w_s[(kk + q) * 68 + n]);
            unsigned b1 = __float_as_uint(w_s[(kk + 4 + q) * 68 + n]);
#pragma unroll
            for (int mt = 0; mt < 8; mt++) {
                int r = mt * 16 + g;
                unsigned a0 = __float_as_uint(a_s[r * 36 + kk + q]);
                unsigned a1 = __float_as_uint(a_s[(r + 8) * 36 + kk + q]);
                unsigned a2 = __float_as_uint(a_s[r * 36 + kk + 4 + q]);
                unsigned a3 = __float_as_uint(a_s[(r + 8) * 36 + kk + 4 + q]);
                mma_tf32(acc[mt], a0, a1, a2, a3, b0, b1);
            }
        }
        __syncthreads();
    }
    // epilogue: h += acc + bias
    int c = n0w + 2 * q;
    float2 bv = *(const float2*)(bias + c);
#pragma unroll
    for (int mt = 0; mt < 8; mt++) {
        int rA = row0 + mt * 16 + g, rB = rA + 8;
        if (rA < NN) {
            float2 hv = *(float2*)(g_h + rA * 64 + c);
            hv.x += acc[mt][0] + bv.x;
            hv.y += acc[mt][1] + bv.y;
            *(float2*)(g_h + rA * 64 + c) = hv;
        }
        if (rB < NN) {
            float2 hv = *(float2*)(g_h + rB * 64 + c);
            hv.x += acc[mt][2] + bv.x;
            hv.y += acc[mt][3] + bv.y;
            *(float2*)(g_h + rB * 64 + c) = hv;
        }
    }
}

// ---------------- pool: run-length max over sorted batch + encoded atomicMax ----------------
__global__ void __launch_bounds__(256) k_pool(const int* __restrict__ batch) {
    int t = threadIdx.x;
    int c = t & 63, sub = t >> 6;
    int n0 = blockIdx.x * 64 + sub * 16;
    float cur = -__int_as_float(0x7f800000);  // -inf
    int curb = -1;
    for (int i = 0; i < 16; i++) {
        int n = n0 + i;
        if (n >= NN) break;
        int b = batch[n];
        if (b != curb) {
            if (curb >= 0) atomicMax(&g_pool[curb * 64 + c], encf(cur));
            curb = b;
            cur = -__int_as_float(0x7f800000);
        }
        cur = fmaxf(cur, g_h[n * 64 + c]);
    }
    if (curb >= 0) atomicMax(&g_pool[curb * 64 + c], encf(cur));
}

// ---------------- final MLP: [64,64] -> relu -> [64,80] ----------------
__global__ void __launch_bounds__(256) k_final(const float* __restrict__ w1,
                                               const float* __restrict__ b1,
                                               const float* __restrict__ w2,
                                               const float* __restrict__ b2,
                                               float* __restrict__ out) {
    __shared__ float g_s[64 * 64];
    __shared__ float t_s[64 * 64];
    int t = threadIdx.x;
    for (int i = t; i < 4096; i += 256) {
        unsigned u = g_pool[i];
        g_s[i] = (u == ENC_NEGINF) ? 0.f : decf(u);
    }
    __syncthreads();
    for (int e = t; e < 4096; e += 256) {
        int r = e >> 6, c = e & 63;
        float a = b1[c];
        for (int k = 0; k < 64; k++) a = fmaf(g_s[r * 64 + k], w1[k * 64 + c], a);
        t_s[e] = fmaxf(a, 0.f);
    }
    __syncthreads();
    for (int e = t; e < 5120; e += 256) {
        int r = e / 80, c = e % 80;
        float a = b2[c];
        for (int k = 0; k < 64; k++) a = fmaf(t_s[r * 64 + k], w2[k * 80 + c], a);
        out[e] = a;
    }
}

// ---------------- launch ----------------
extern "C" void kernel_launch(void* const* d_in, const int* in_sizes, int n_in,
                              void* d_out, int out_size) {
    const float* x    = (const float*)d_in[0];
    const int*   ei   = (const int*)d_in[1];
    const int*   batch = (const int*)d_in[2];
    const float* cw1  = (const float*)d_in[3];
    const float* cb1  = (const float*)d_in[4];
    const float* cg1  = (const float*)d_in[5];
    const float* cbe1 = (const float*)d_in[6];
    const float* cw2  = (const float*)d_in[7];
    const float* cb2  = (const float*)d_in[8];
    const float* Lw1  = (const float*)d_in[9];
    const float* Lb1  = (const float*)d_in[10];
    const float* Lg1  = (const float*)d_in[11];
    const float* Lbe1 = (const float*)d_in[12];
    const float* Lw2  = (const float*)d_in[13];
    const float* Lb2  = (const float*)d_in[14];
    const float* mw1  = (const float*)d_in[15];
    const float* mb1  = (const float*)d_in[16];
    const float* mw2  = (const float*)d_in[17];
    const float* mb2  = (const float*)d_in[18];
    float* out = (float*)d_out;

    const int* src = ei;
    const int* dst = ei + EE;

    // CSR build
    k_init<<<391, 256>>>();
    k_deg<<<EE / 256, 256>>>(dst);
    k_scan1<<<98, 1024>>>();
    k_scan2<<<1, 128>>>();
    k_scan3<<<391, 256>>>();
    k_scatter<<<EE / 256, 256>>>(src, dst);

    // layer 0 (6 -> 12 -> 64), h = relu(genconv(x))
    k_l0<<<391, 256>>>(x, cw1, cb1);
    k_bnfin<<<1, 32>>>(cg1, cbe1, 12, 391);
    k_l0_mlp2<<<391, 256>>>(cw2, cb2);

    // layers 1..3: h += genconv(relu(h))
    for (int i = 0; i < 3; i++) {
        k_agg64<<<12500, 256>>>();
        k_gemm1<<<782, 256>>>(Lw1 + i * 64 * 128, Lb1 + i * 128);
        k_bnfin<<<1, 128>>>(Lg1 + i * 128, Lbe1 + i * 128, 128, 782);
        k_gemm2<<<782, 256>>>(Lw2 + i * 128 * 64, Lb2 + i * 64);
    }

    k_pool<<<1563, 256>>>(batch);
    k_final<<<1, 256>>>(mw1, mb1, mw2, mb2, out);
}

// round 4
// speedup vs baseline: 1.3929x; 1.0687x over previous
#include <cuda_runtime.h>

#define NN 100000
#define EE 1600000
#define BB 64
#define EPS_MSG 1e-7f
#define ENC_NEGINF 0x007FFFFFu

// ---------------- scratch (static __device__, no allocations) ----------------
__device__ float g_h[NN * 64];        // node state h
__device__ float g_out64[NN * 64];    // agg + residual (GEMM1 input)
__device__ float g_hidden[NN * 128];  // MLP hidden (also reused as [N,12] for layer 0)
__device__ int   g_deg[NN];
__device__ int   g_tmp[NN];
__device__ int   g_rowptr[NN + 1];
__device__ int   g_pos[NN];
__device__ int   g_col[EE];
__device__ int   g_bsum[128];
__device__ int   g_bscan[128];
__device__ float g_psum[2048 * 128];
__device__ float g_psumsq[2048 * 128];
__device__ float g_scale[128];
__device__ float g_shift[128];
__device__ unsigned g_pool[BB * 64];
__device__ int   g_ctr;   // last-block counter (reset to 0 by last block each use)

// ---------------- helpers ----------------
__device__ __forceinline__ unsigned encf(float f) {
    unsigned u = __float_as_uint(f);
    return (u & 0x80000000u) ? ~u : (u | 0x80000000u);
}
__device__ __forceinline__ float decf(unsigned u) {
    return __uint_as_float((u & 0x80000000u) ? (u ^ 0x80000000u) : ~u);
}
__device__ __forceinline__ float f2tf(float x) {
    unsigned r;
    asm("cvt.rna.tf32.f32 %0, %1;" : "=r"(r) : "f"(x));
    return __uint_as_float(r);
}
__device__ __forceinline__ void mma_tf32(float* d, unsigned a0, unsigned a1,
                                         unsigned a2, unsigned a3,
                                         unsigned b0, unsigned b1) {
    asm volatile(
        "mma.sync.aligned.m16n8k8.row.col.f32.tf32.tf32.f32 "
        "{%0,%1,%2,%3}, {%4,%5,%6,%7}, {%8,%9}, {%0,%1,%2,%3};"
        : "+f"(d[0]), "+f"(d[1]), "+f"(d[2]), "+f"(d[3])
        : "r"(a0), "r"(a1), "r"(a2), "r"(a3), "r"(b0), "r"(b1));
}

// online softmax accumulate (used only in layer-0 F=6 path)
#define ONLINE_UPD(v, m, p, q)                       \
    do {                                             \
        if ((v) <= (m)) {                            \
            float _e = __expf((v) - (m));            \
            (p) += _e;                               \
            (q) = fmaf((v), _e, (q));                \
        } else {                                     \
            float _s = __expf((m) - (v));            \
            (p) = fmaf((p), _s, 1.f);                \
            (q) = fmaf((q), _s, (v));                \
            (m) = (v);                               \
        }                                            \
    } while (0)

// ---------------- init ----------------
__global__ void k_init() {
    int i = blockIdx.x * blockDim.x + threadIdx.x;
    if (i < NN) g_deg[i] = 0;
    if (i < BB * 64) g_pool[i] = ENC_NEGINF;
}

// ---------------- CSR build ----------------
__global__ void k_deg(const int* __restrict__ dst) {
    int e = blockIdx.x * blockDim.x + threadIdx.x;
    if (e < EE) atomicAdd(&g_deg[dst[e]], 1);
}

__global__ void __launch_bounds__(1024) k_scan1() {
    __shared__ int s[1024];
    int t = threadIdx.x;
    int idx = blockIdx.x * 1024 + t;
    int v = (idx < NN) ? g_deg[idx] : 0;
    s[t] = v;
    __syncthreads();
    for (int off = 1; off < 1024; off <<= 1) {
        int a = (t >= off) ? s[t - off] : 0;
        __syncthreads();
        s[t] += a;
        __syncthreads();
    }
    if (idx < NN) g_tmp[idx] = s[t];
    if (t == 1023) g_bsum[blockIdx.x] = s[1023];
}

__global__ void k_scan2() {
    __shared__ int s[128];
    int t = threadIdx.x;
    int v = (t < 98) ? g_bsum[t] : 0;
    s[t] = v;
    __syncthreads();
    for (int off = 1; off < 128; off <<= 1) {
        int a = (t >= off) ? s[t - off] : 0;
        __syncthreads();
        s[t] += a;
        __syncthreads();
    }
    g_bscan[t] = s[t];
}

__global__ void k_scan3() {
    int idx = blockIdx.x * blockDim.x + threadIdx.x;
    if (idx >= NN) return;
    int b = idx >> 10;
    int off = (b > 0) ? g_bscan[b - 1] : 0;
    int incl = g_tmp[idx] + off;
    g_rowptr[idx + 1] = incl;
    g_pos[idx] = incl - g_deg[idx];
    if (idx == 0) g_rowptr[0] = 0;
}

__global__ void k_scatter(const int* __restrict__ src, const int* __restrict__ dst) {
    int e = blockIdx.x * blockDim.x + threadIdx.x;
    if (e >= EE) return;
    int p = atomicAdd(&g_pos[dst[e]], 1);
    g_col[p] = src[e];
}

// ---------------- layer 0: fused agg(F=6) + MLP1 (6->12) + BN stats + finalize ----------------
__global__ void __launch_bounds__(256) k_l0(const float* __restrict__ x,
                                            const float* __restrict__ w1,
                                            const float* __restrict__ b1,
                                            const float* __restrict__ gam,
                                            const float* __restrict__ bet) {
    __shared__ float w_s[72];
    __shared__ float sacc[12], sacc2[12];
    __shared__ int isLast;
    int t = threadIdx.x;
    if (t < 72) w_s[t] = w1[t];
    if (t < 12) { sacc[t] = 0.f; sacc2[t] = 0.f; }
    __syncthreads();

    int n = blockIdx.x * 256 + t;
    float hid[12];
#pragma unroll
    for (int j = 0; j < 12; j++) hid[j] = 0.f;

    if (n < NN) {
        int beg = g_rowptr[n], end = g_rowptr[n + 1];
        float m[6], p[6], q[6];
#pragma unroll
        for (int c = 0; c < 6; c++) { m[c] = 0.f; p[c] = 0.f; q[c] = 0.f; }
        for (int e = beg; e < end; e++) {
            int s = g_col[e];
#pragma unroll
            for (int c = 0; c < 6; c++) {
                float v = fmaxf(x[s * 6 + c], 0.f) + EPS_MSG;
                ONLINE_UPD(v, m[c], p[c], q[c]);
            }
        }
        float o[6];
#pragma unroll
        for (int c = 0; c < 6; c++) o[c] = q[c] / (p[c] + 1e-16f) + x[n * 6 + c];
#pragma unroll
        for (int j = 0; j < 12; j++) {
            float a = b1[j];
#pragma unroll
            for (int c = 0; c < 6; c++) a = fmaf(o[c], w_s[c * 12 + j], a);
            hid[j] = a;
            g_hidden[n * 12 + j] = a;
        }
    }
#pragma unroll
    for (int j = 0; j < 12; j++) {
        float v = hid[j], v2 = v * v;
        for (int off = 16; off; off >>= 1) {
            v += __shfl_down_sync(0xffffffffu, v, off);
            v2 += __shfl_down_sync(0xffffffffu, v2, off);
        }
        if ((t & 31) == 0) { atomicAdd(&sacc[j], v); atomicAdd(&sacc2[j], v2); }
    }
    __syncthreads();
    if (t < 12) {
        g_psum[blockIdx.x * 12 + t] = sacc[t];
        g_psumsq[blockIdx.x * 12 + t] = sacc2[t];
    }
    // last-block BN finalize
    __threadfence();
    if (t == 0) isLast = (atomicAdd(&g_ctr, 1) == (int)gridDim.x - 1);
    __syncthreads();
    if (isLast) {
        if (t == 0) g_ctr = 0;
        if (t < 12) {
            float s = 0.f, s2 = 0.f;
            for (int i = 0; i < (int)gridDim.x; i++) {
                s += g_psum[i * 12 + t];
                s2 += g_psumsq[i * 12 + t];
            }
            float mu = s / (float)NN;
            float var = fmaxf(s2 / (float)NN - mu * mu, 0.f);
            float sc = gam[t] * rsqrtf(var + 1e-5f);
            g_scale[t] = sc;
            g_shift[t] = bet[t] - mu * sc;
        }
    }
}

// ---------------- layer 0 MLP2: relu(bn(hid12)) @ w2[12,64] + b2 -> h = relu(.) ----------------
__global__ void __launch_bounds__(256) k_l0_mlp2(const float* __restrict__ w2,
                                                 const float* __restrict__ b2) {
    __shared__ float w_s[12 * 64];
    __shared__ float b_s[64];
    int t = threadIdx.x;
    for (int i = t; i < 768; i += 256) w_s[i] = w2[i];
    if (t < 64) b_s[t] = b2[t];
    __syncthreads();
    int n = blockIdx.x * 256 + t;
    if (n >= NN) return;
    float v[12];
#pragma unroll
    for (int j = 0; j < 12; j++)
        v[j] = fmaxf(fmaf(g_hidden[n * 12 + j], g_scale[j], g_shift[j]), 0.f);
    for (int c0 = 0; c0 < 64; c0 += 4) {
        float a0 = b_s[c0], a1 = b_s[c0 + 1], a2 = b_s[c0 + 2], a3 = b_s[c0 + 3];
#pragma unroll
        for (int j = 0; j < 12; j++) {
            float vj = v[j];
            a0 = fmaf(vj, w_s[j * 64 + c0], a0);
            a1 = fmaf(vj, w_s[j * 64 + c0 + 1], a1);
            a2 = fmaf(vj, w_s[j * 64 + c0 + 2], a2);
            a3 = fmaf(vj, w_s[j * 64 + c0 + 3], a3);
        }
        float4 o;
        o.x = fmaxf(a0, 0.f); o.y = fmaxf(a1, 0.f);
        o.z = fmaxf(a2, 0.f); o.w = fmaxf(a3, 0.f);
        *(float4*)(g_h + n * 64 + c0) = o;
    }
}

// ---------------- aggregation, F=64: warp/node, two-phase, float4, half-warp/edge --------
// lanes 0-15 process even edges, 16-31 odd edges; each lane owns 4 channels (li*4..+3).
__global__ void __launch_bounds__(256) k_agg64() {
    int gt = blockIdx.x * blockDim.x + threadIdx.x;
    int n = gt >> 5;
    if (n >= NN) return;
    int lane = gt & 31;
    int half = lane >> 4, li = lane & 15;
    int beg = g_rowptr[n], end = g_rowptr[n + 1];
    const float4* __restrict__ H = (const float4*)g_h;

    // phase 1: channel max of relu(h)+eps over this half's edges
    float mx = 0.f, my = 0.f, mz = 0.f, mw = 0.f;
    int e = beg + half;
    for (; e + 2 < end; e += 4) {
        int i0 = g_col[e], i1 = g_col[e + 2];
        float4 v0 = H[i0 * 16 + li];
        float4 v1 = H[i1 * 16 + li];
        mx = fmaxf(mx, fmaxf(fmaxf(v0.x, 0.f), fmaxf(v1.x, 0.f)));
        my = fmaxf(my, fmaxf(fmaxf(v0.y, 0.f), fmaxf(v1.y, 0.f)));
        mz = fmaxf(mz, fmaxf(fmaxf(v0.z, 0.f), fmaxf(v1.z, 0.f)));
        mw = fmaxf(mw, fmaxf(fmaxf(v0.w, 0.f), fmaxf(v1.w, 0.f)));
    }
    for (; e < end; e += 2) {
        int i0 = g_col[e];
        float4 v0 = H[i0 * 16 + li];
        mx = fmaxf(mx, fmaxf(v0.x, 0.f));
        my = fmaxf(my, fmaxf(v0.y, 0.f));
        mz = fmaxf(mz, fmaxf(v0.z, 0.f));
        mw = fmaxf(mw, fmaxf(v0.w, 0.f));
    }
    // merge halves (same channels, different edge subsets)
    mx = fmaxf(mx, __shfl_xor_sync(0xffffffffu, mx, 16));
    my = fmaxf(my, __shfl_xor_sync(0xffffffffu, my, 16));
    mz = fmaxf(mz, __shfl_xor_sync(0xffffffffu, mz, 16));
    mw = fmaxf(mw, __shfl_xor_sync(0xffffffffu, mw, 16));
    mx += EPS_MSG; my += EPS_MSG; mz += EPS_MSG; mw += EPS_MSG;

    // phase 2: exp sums (branch-free)
    float px = 0.f, py = 0.f, pz = 0.f, pw = 0.f;
    float qx = 0.f, qy = 0.f, qz = 0.f, qw = 0.f;
    e = beg + half;
    for (; e + 2 < end; e += 4) {
        int i0 = g_col[e], i1 = g_col[e + 2];
        float4 v0 = H[i0 * 16 + li];
        float4 v1 = H[i1 * 16 + li];
        float a, ex;
        a = fmaxf(v0.x, 0.f) + EPS_MSG; ex = __expf(a - mx); px += ex; qx = fmaf(a, ex, qx);
        a = fmaxf(v0.y, 0.f) + EPS_MSG; ex = __expf(a - my); py += ex; qy = fmaf(a, ex, qy);
        a = fmaxf(v0.z, 0.f) + EPS_MSG; ex = __expf(a - mz); pz += ex; qz = fmaf(a, ex, qz);
        a = fmaxf(v0.w, 0.f) + EPS_MSG; ex = __expf(a - mw); pw += ex; qw = fmaf(a, ex, qw);
        a = fmaxf(v1.x, 0.f) + EPS_MSG; ex = __expf(a - mx); px += ex; qx = fmaf(a, ex, qx);
        a = fmaxf(v1.y, 0.f) + EPS_MSG; ex = __expf(a - my); py += ex; qy = fmaf(a, ex, qy);
        a = fmaxf(v1.z, 0.f) + EPS_MSG; ex = __expf(a - mz); pz += ex; qz = fmaf(a, ex, qz);
        a = fmaxf(v1.w, 0.f) + EPS_MSG; ex = __expf(a - mw); pw += ex; qw = fmaf(a, ex, qw);
    }
    for (; e < end; e += 2) {
        int i0 = g_col[e];
        float4 v0 = H[i0 * 16 + li];
        float a, ex;
        a = fmaxf(v0.x, 0.f) + EPS_MSG; ex = __expf(a - mx); px += ex; qx = fmaf(a, ex, qx);
        a = fmaxf(v0.y, 0.f) + EPS_MSG; ex = __expf(a - my); py += ex; qy = fmaf(a, ex, qy);
        a = fmaxf(v0.z, 0.f) + EPS_MSG; ex = __expf(a - mz); pz += ex; qz = fmaf(a, ex, qz);
        a = fmaxf(v0.w, 0.f) + EPS_MSG; ex = __expf(a - mw); pw += ex; qw = fmaf(a, ex, qw);
    }
    px += __shfl_xor_sync(0xffffffffu, px, 16);
    py += __shfl_xor_sync(0xffffffffu, py, 16);
    pz += __shfl_xor_sync(0xffffffffu, pz, 16);
    pw += __shfl_xor_sync(0xffffffffu, pw, 16);
    qx += __shfl_xor_sync(0xffffffffu, qx, 16);
    qy += __shfl_xor_sync(0xffffffffu, qy, 16);
    qz += __shfl_xor_sync(0xffffffffu, qz, 16);
    qw += __shfl_xor_sync(0xffffffffu, qw, 16);

    if (half == 0) {
        float4 r = H[n * 16 + li];
        float4 o;
        o.x = qx / (px + 1e-16f) + fmaxf(r.x, 0.f);
        o.y = qy / (py + 1e-16f) + fmaxf(r.y, 0.f);
        o.z = qz / (pz + 1e-16f) + fmaxf(r.z, 0.f);
        o.w = qw / (pw + 1e-16f) + fmaxf(r.w, 0.f);
        ((float4*)g_out64)[n * 16 + li] = o;
    }
}

// ---------------- GEMM1 (tf32 mma): g_out64[N,64] @ W[64,128] + b -> g_hidden[N,128]
// Fused BN partial stats + last-block finalize.
__global__ void __launch_bounds__(256) k_gemm1(const float* __restrict__ W,
                                               const float* __restrict__ bias,
                                               const float* __restrict__ gam,
                                               const float* __restrict__ bet) {
    __shared__ float a_s[128 * 36];   // [row][k] stride 36
    __shared__ float w_s[32 * 132];   // [k][n] stride 132
    __shared__ int isLast;
    int t = threadIdx.x, lane = t & 31, warp = t >> 5;
    int q = lane & 3, g = lane >> 2;
    int row0 = blockIdx.x * 128;
    int n0w = warp * 16;
    float acc[8][2][4];
#pragma unroll
    for (int i = 0; i < 8; i++)
#pragma unroll
        for (int j = 0; j < 2; j++)
#pragma unroll
            for (int k = 0; k < 4; k++) acc[i][j][k] = 0.f;

    for (int kc = 0; kc < 64; kc += 32) {
#pragma unroll
        for (int i = t; i < 1024; i += 256) {
            int r = i >> 3, kk = (i & 7) << 2;
            int row = row0 + r;
            float4 v = make_float4(0.f, 0.f, 0.f, 0.f);
            if (row < NN) v = *(const float4*)(g_out64 + row * 64 + kc + kk);
            float4 o;
            o.x = f2tf(v.x); o.y = f2tf(v.y); o.z = f2tf(v.z); o.w = f2tf(v.w);
            *(float4*)(a_s + r * 36 + kk) = o;
        }
#pragma unroll
        for (int i = t; i < 1024; i += 256) {
            int kl = i >> 5, n4 = (i & 31) << 2;
            float4 v = *(const float4*)(W + (kc + kl) * 128 + n4);
            float4 o;
            o.x = f2tf(v.x); o.y = f2tf(v.y); o.z = f2tf(v.z); o.w = f2tf(v.w);
            *(float4*)(w_s + kl * 132 + n4) = o;
        }
        __syncthreads();
#pragma unroll
        for (int kk = 0; kk < 32; kk += 8) {
            unsigned b[2][2];
#pragma unroll
            for (int nt = 0; nt < 2; nt++) {
                int n = n0w + nt * 8 + g;
                b[nt][0] = __float_as_uint(w_s[(kk + q) * 132 + n]);
                b[nt][1] = __float_as_uint(w_s[(kk + 4 + q) * 132 + n]);
            }
#pragma unroll
            for (int mt = 0; mt < 8; mt++) {
                int r = mt * 16 + g;
                unsigned a0 = __float_as_uint(a_s[r * 36 + kk + q]);
                unsigned a1 = __float_as_uint(a_s[(r + 8) * 36 + kk + q]);
                unsigned a2 = __float_as_uint(a_s[r * 36 + kk + 4 + q]);
                unsigned a3 = __float_as_uint(a_s[(r + 8) * 36 + kk + 4 + q]);
                mma_tf32(acc[mt][0], a0, a1, a2, a3, b[0][0], b[0][1]);
                mma_tf32(acc[mt][1], a0, a1, a2, a3, b[1][0], b[1][1]);
            }
        }
        __syncthreads();
    }
    // epilogue: +bias, store, fused BN partial stats
#pragma unroll
    for (int nt = 0; nt < 2; nt++) {
        int c = n0w + nt * 8 + 2 * q;
        float2 bv = *(const float2*)(bias + c);
        float s0 = 0.f, s1 = 0.f, s20 = 0.f, s21 = 0.f;
#pragma unroll
        for (int mt = 0; mt < 8; mt++) {
            int rA = row0 + mt * 16 + g, rB = rA + 8;
            float v0 = acc[mt][nt][0] + bv.x, v1 = acc[mt][nt][1] + bv.y;
            float v2 = acc[mt][nt][2] + bv.x, v3 = acc[mt][nt][3] + bv.y;
            if (rA < NN) {
                *(float2*)(g_hidden + rA * 128 + c) = make_float2(v0, v1);
                s0 += v0; s20 = fmaf(v0, v0, s20);
                s1 += v1; s21 = fmaf(v1, v1, s21);
            }
            if (rB < NN) {
                *(float2*)(g_hidden + rB * 128 + c) = make_float2(v2, v3);
                s0 += v2; s20 = fmaf(v2, v2, s20);
                s1 += v3; s21 = fmaf(v3, v3, s21);
            }
        }
#pragma unroll
        for (int off = 16; off >= 4; off >>= 1) {
            s0 += __shfl_down_sync(0xffffffffu, s0, off);
            s1 += __shfl_down_sync(0xffffffffu, s1, off);
            s20 += __shfl_down_sync(0xffffffffu, s20, off);
            s21 += __shfl_down_sync(0xffffffffu, s21, off);
        }
        if (lane < 4) {
            int cc = n0w + nt * 8 + 2 * lane;
            g_psum[blockIdx.x * 128 + cc] = s0;
            g_psum[blockIdx.x * 128 + cc + 1] = s1;
            g_psumsq[blockIdx.x * 128 + cc] = s20;
            g_psumsq[blockIdx.x * 128 + cc + 1] = s21;
        }
    }
    // last-block BN finalize
    __threadfence();
    if (t == 0) isLast = (atomicAdd(&g_ctr, 1) == (int)gridDim.x - 1);
    __syncthreads();
    if (isLast) {
        if (t == 0) g_ctr = 0;
        if (t < 128) {
            float s = 0.f, s2 = 0.f;
            int nb = (int)gridDim.x;
#pragma unroll 4
            for (int i = 0; i < nb; i++) {
                s += g_psum[i * 128 + t];
                s2 += g_psumsq[i * 128 + t];
            }
            float mu = s / (float)NN;
            float var = fmaxf(s2 / (float)NN - mu * mu, 0.f);
            float sc = gam[t] * rsqrtf(var + 1e-5f);
            g_scale[t] = sc;
            g_shift[t] = bet[t] - mu * sc;
        }
    }
}

// ---------------- GEMM2 (tf32 mma): relu(bn(g_hidden))[N,128] @ W[128,64] + b; h += .
__global__ void __launch_bounds__(256) k_gemm2(const float* __restrict__ W,
                                               const float* __restrict__ bias) {
    __shared__ float a_s[128 * 36];   // [row][k] stride 36
    __shared__ float w_s[32 * 68];    // [k][n] stride 68
    int t = threadIdx.x, lane = t & 31, warp = t >> 5;
    int q = lane & 3, g = lane >> 2;
    int row0 = blockIdx.x * 128;
    int n0w = warp * 8;
    float acc[8][4];
#pragma unroll
    for (int i = 0; i < 8; i++)
#pragma unroll
        for (int k = 0; k < 4; k++) acc[i][k] = 0.f;

    for (int kc = 0; kc < 128; kc += 32) {
#pragma unroll
        for (int i = t; i < 1024; i += 256) {
            int r = i >> 3, kk = (i & 7) << 2;
            int row = row0 + r;
            float4 o = make_float4(0.f, 0.f, 0.f, 0.f);
            if (row < NN) {
                float4 hv = *(const float4*)(g_hidden + row * 128 + kc + kk);
                float4 sc = *(const float4*)(g_scale + kc + kk);
                float4 sh = *(const float4*)(g_shift + kc + kk);
                o.x = f2tf(fmaxf(fmaf(hv.x, sc.x, sh.x), 0.f));
                o.y = f2tf(fmaxf(fmaf(hv.y, sc.y, sh.y), 0.f));
                o.z = f2tf(fmaxf(fmaf(hv.z, sc.z, sh.z), 0.f));
                o.w = f2tf(fmaxf(fmaf(hv.w, sc.w, sh.w), 0.f));
            }
            *(float4*)(a_s + r * 36 + kk) = o;
        }
#pragma unroll
        for (int i = t; i < 512; i += 256) {
            int kl = i >> 4, n4 = (i & 15) << 2;
            float4 v = *(const float4*)(W + (kc + kl) * 64 + n4);
            float4 o;
            o.x = f2tf(v.x); o.y = f2tf(v.y); o.z = f2tf(v.z); o.w = f2tf(v.w);
            *(float4*)(w_s + kl * 68 + n4) = o;
        }
        __syncthreads();
#pragma unroll
        for (int kk = 0; kk < 32; kk += 8) {
            int n = n0w + g;
            unsigned b0 = __float_as_uint(w_s[(kk + q) * 68 + n]);
            unsigned b1 = __float_as_uint(w_s[(kk + 4 + q) * 68 + n]);
#pragma unroll
            for (int mt = 0; mt < 8; mt++) {
                int r = mt * 16 + g;
                unsigned a0 = __float_as_uint(a_s[r * 36 + kk + q]);
                unsigned a1 = __float_as_uint(a_s[(r + 8) * 36 + kk + q]);
                unsigned a2 = __float_as_uint(a_s[r * 36 + kk + 4 + q]);
                unsigned a3 = __float_as_uint(a_s[(r + 8) * 36 + kk + 4 + q]);
                mma_tf32(acc[mt], a0, a1, a2, a3, b0, b1);
            }
        }
        __syncthreads();
    }
    int c = n0w + 2 * q;
    float2 bv = *(const float2*)(bias + c);
#pragma unroll
    for (int mt = 0; mt < 8; mt++) {
        int rA = row0 + mt * 16 + g, rB = rA + 8;
        if (rA < NN) {
            float2 hv = *(float2*)(g_h + rA * 64 + c);
            hv.x += acc[mt][0] + bv.x;
            hv.y += acc[mt][1] + bv.y;
            *(float2*)(g_h + rA * 64 + c) = hv;
        }
        if (rB < NN) {
            float2 hv = *(float2*)(g_h + rB * 64 + c);
            hv.x += acc[mt][2] + bv.x;
            hv.y += acc[mt][3] + bv.y;
            *(float2*)(g_h + rB * 64 + c) = hv;
        }
    }
}

// ---------------- pool: run-length max over sorted batch + encoded atomicMax ----------------
__global__ void __launch_bounds__(256) k_pool(const int* __restrict__ batch) {
    int t = threadIdx.x;
    int c = t & 63, sub = t >> 6;
    int n0 = blockIdx.x * 64 + sub * 16;
    float cur = -__int_as_float(0x7f800000);  // -inf
    int curb = -1;
    for (int i = 0; i < 16; i++) {
        int n = n0 + i;
        if (n >= NN) break;
        int b = batch[n];
        if (b != curb) {
            if (curb >= 0) atomicMax(&g_pool[curb * 64 + c], encf(cur));
            curb = b;
            cur = -__int_as_float(0x7f800000);
        }
        cur = fmaxf(cur, g_h[n * 64 + c]);
    }
    if (curb >= 0) atomicMax(&g_pool[curb * 64 + c], encf(cur));
}

// ---------------- final MLP: [64,64] -> relu -> [64,80] ----------------
__global__ void __launch_bounds__(256) k_final(const float* __restrict__ w1,
                                               const float* __restrict__ b1,
                                               const float* __restrict__ w2,
                                               const float* __restrict__ b2,
                                               float* __restrict__ out) {
    __shared__ float g_s[64 * 64];
    __shared__ float t_s[64 * 64];
    int t = threadIdx.x;
    for (int i = t; i < 4096; i += 256) {
        unsigned u = g_pool[i];
        g_s[i] = (u == ENC_NEGINF) ? 0.f : decf(u);
    }
    __syncthreads();
    for (int e = t; e < 4096; e += 256) {
        int r = e >> 6, c = e & 63;
        float a = b1[c];
        for (int k = 0; k < 64; k++) a = fmaf(g_s[r * 64 + k], w1[k * 64 + c], a);
        t_s[e] = fmaxf(a, 0.f);
    }
    __syncthreads();
    for (int e = t; e < 5120; e += 256) {
        int r = e / 80, c = e % 80;
        float a = b2[c];
        for (int k = 0; k < 64; k++) a = fmaf(t_s[r * 64 + k], w2[k * 80 + c], a);
        out[e] = a;
    }
}

// ---------------- launch ----------------
extern "C" void kernel_launch(void* const* d_in, const int* in_sizes, int n_in,
                              void* d_out, int out_size) {
    const float* x    = (const float*)d_in[0];
    const int*   ei   = (const int*)d_in[1];
    const int*   batch = (const int*)d_in[2];
    const float* cw1  = (const float*)d_in[3];
    const float* cb1  = (const float*)d_in[4];
    const float* cg1  = (const float*)d_in[5];
    const float* cbe1 = (const float*)d_in[6];
    const float* cw2  = (const float*)d_in[7];
    const float* cb2  = (const float*)d_in[8];
    const float* Lw1  = (const float*)d_in[9];
    const float* Lb1  = (const float*)d_in[10];
    const float* Lg1  = (const float*)d_in[11];
    const float* Lbe1 = (const float*)d_in[12];
    const float* Lw2  = (const float*)d_in[13];
    const float* Lb2  = (const float*)d_in[14];
    const float* mw1  = (const float*)d_in[15];
    const float* mb1  = (const float*)d_in[16];
    const float* mw2  = (const float*)d_in[17];
    const float* mb2  = (const float*)d_in[18];
    float* out = (float*)d_out;

    const int* src = ei;
    const int* dst = ei + EE;

    // CSR build
    k_init<<<391, 256>>>();
    k_deg<<<EE / 256, 256>>>(dst);
    k_scan1<<<98, 1024>>>();
    k_scan2<<<1, 128>>>();
    k_scan3<<<391, 256>>>();
    k_scatter<<<EE / 256, 256>>>(src, dst);

    // layer 0 (6 -> 12 -> 64), h = relu(genconv(x))
    k_l0<<<391, 256>>>(x, cw1, cb1, cg1, cbe1);
    k_l0_mlp2<<<391, 256>>>(cw2, cb2);

    // layers 1..3: h += genconv(relu(h))
    for (int i = 0; i < 3; i++) {
        k_agg64<<<12500, 256>>>();
        k_gemm1<<<782, 256>>>(Lw1 + i * 64 * 128, Lb1 + i * 128,
                              Lg1 + i * 128, Lbe1 + i * 128);
        k_gemm2<<<782, 256>>>(Lw2 + i * 128 * 64, Lb2 + i * 64);
    }

    k_pool<<<1563, 256>>>(batch);
    k_final<<<1, 256>>>(mw1, mb1, mw2, mb2, out);
}

// round 5
// speedup vs baseline: 1.5899x; 1.1414x over previous
#include <cuda_runtime.h>

#define NN 100000
#define EE 1600000
#define BB 64
#define EPS_MSG 1e-7f
#define ENC_NEGINF 0x007FFFFFu

// ---------------- scratch (static __device__, no allocations) ----------------
__device__ float g_h[NN * 64];        // node state h
__device__ float g_out64[NN * 64];    // agg + residual (GEMM1 input)
__device__ float g_hidden[NN * 128];  // MLP hidden (also reused as [N,12] for layer 0)
__device__ float g_x8[NN * 8];        // relu(x)+eps padded to 8 (layer-0 messages)
__device__ int   g_deg[NN];
__device__ int   g_tmp[NN];
__device__ int   g_rowptr[NN + 1];
__device__ int   g_pos[NN];
__device__ int   g_col[EE];
__device__ int   g_bsum[128];
__device__ int   g_bscan[128];
__device__ float g_psum[2048 * 128];
__device__ float g_psumsq[2048 * 128];
__device__ float g_scale[128];
__device__ float g_shift[128];
__device__ unsigned g_pool[BB * 64];
__device__ int   g_ctr;   // last-block counter (reset to 0 by last block each use)

// ---------------- helpers ----------------
__device__ __forceinline__ unsigned encf(float f) {
    unsigned u = __float_as_uint(f);
    return (u & 0x80000000u) ? ~u : (u | 0x80000000u);
}
__device__ __forceinline__ float decf(unsigned u) {
    return __uint_as_float((u & 0x80000000u) ? (u ^ 0x80000000u) : ~u);
}
__device__ __forceinline__ float f2tf(float x) {
    unsigned r;
    asm("cvt.rna.tf32.f32 %0, %1;" : "=r"(r) : "f"(x));
    return __uint_as_float(r);
}
__device__ __forceinline__ void mma_tf32(float* d, unsigned a0, unsigned a1,
                                         unsigned a2, unsigned a3,
                                         unsigned b0, unsigned b1) {
    asm volatile(
        "mma.sync.aligned.m16n8k8.row.col.f32.tf32.tf32.f32 "
        "{%0,%1,%2,%3}, {%4,%5,%6,%7}, {%8,%9}, {%0,%1,%2,%3};"
        : "+f"(d[0]), "+f"(d[1]), "+f"(d[2]), "+f"(d[3])
        : "r"(a0), "r"(a1), "r"(a2), "r"(a3), "r"(b0), "r"(b1));
}

// ---------------- init: zero deg/pool, build padded layer-0 messages ----------------
__global__ void k_init(const float* __restrict__ x) {
    int i = blockIdx.x * blockDim.x + threadIdx.x;
    if (i < NN) {
        g_deg[i] = 0;
        float4 a, b;
        a.x = fmaxf(x[i * 6 + 0], 0.f) + EPS_MSG;
        a.y = fmaxf(x[i * 6 + 1], 0.f) + EPS_MSG;
        a.z = fmaxf(x[i * 6 + 2], 0.f) + EPS_MSG;
        a.w = fmaxf(x[i * 6 + 3], 0.f) + EPS_MSG;
        b.x = fmaxf(x[i * 6 + 4], 0.f) + EPS_MSG;
        b.y = fmaxf(x[i * 6 + 5], 0.f) + EPS_MSG;
        b.z = 0.f; b.w = 0.f;
        ((float4*)g_x8)[i * 2] = a;
        ((float4*)g_x8)[i * 2 + 1] = b;
    }
    if (i < BB * 64) g_pool[i] = ENC_NEGINF;
}

// ---------------- CSR build ----------------
__global__ void k_deg(const int* __restrict__ dst) {
    int e = blockIdx.x * blockDim.x + threadIdx.x;
    if (e < EE) atomicAdd(&g_deg[dst[e]], 1);
}

__global__ void __launch_bounds__(1024) k_scan1() {
    __shared__ int s[1024];
    int t = threadIdx.x;
    int idx = blockIdx.x * 1024 + t;
    int v = (idx < NN) ? g_deg[idx] : 0;
    s[t] = v;
    __syncthreads();
    for (int off = 1; off < 1024; off <<= 1) {
        int a = (t >= off) ? s[t - off] : 0;
        __syncthreads();
        s[t] += a;
        __syncthreads();
    }
    if (idx < NN) g_tmp[idx] = s[t];
    if (t == 1023) g_bsum[blockIdx.x] = s[1023];
}

__global__ void k_scan2() {
    __shared__ int s[128];
    int t = threadIdx.x;
    int v = (t < 98) ? g_bsum[t] : 0;
    s[t] = v;
    __syncthreads();
    for (int off = 1; off < 128; off <<= 1) {
        int a = (t >= off) ? s[t - off] : 0;
        __syncthreads();
        s[t] += a;
        __syncthreads();
    }
    g_bscan[t] = s[t];
}

__global__ void k_scan3() {
    int idx = blockIdx.x * blockDim.x + threadIdx.x;
    if (idx >= NN) return;
    int b = idx >> 10;
    int off = (b > 0) ? g_bscan[b - 1] : 0;
    int incl = g_tmp[idx] + off;
    g_rowptr[idx + 1] = incl;
    g_pos[idx] = incl - g_deg[idx];
    if (idx == 0) g_rowptr[0] = 0;
}

__global__ void k_scatter(const int* __restrict__ src, const int* __restrict__ dst) {
    int e = blockIdx.x * blockDim.x + threadIdx.x;
    if (e >= EE) return;
    int p = atomicAdd(&g_pos[dst[e]], 1);
    g_col[p] = src[e];
}

// ---------------- layer 0: agg(F=6, shift-free softmax) + MLP1 (6->12) + BN ----------------
__global__ void __launch_bounds__(256) k_l0(const float* __restrict__ x,
                                            const float* __restrict__ w1,
                                            const float* __restrict__ b1,
                                            const float* __restrict__ gam,
                                            const float* __restrict__ bet) {
    __shared__ float w_s[72];
    __shared__ float sacc[12], sacc2[12];
    __shared__ int isLast;
    int t = threadIdx.x;
    if (t < 72) w_s[t] = w1[t];
    if (t < 12) { sacc[t] = 0.f; sacc2[t] = 0.f; }
    __syncthreads();

    int n = blockIdx.x * 256 + t;
    float hid[12];
#pragma unroll
    for (int j = 0; j < 12; j++) hid[j] = 0.f;

    if (n < NN) {
        int beg = g_rowptr[n], end = g_rowptr[n + 1];
        float p[6], q[6];
#pragma unroll
        for (int c = 0; c < 6; c++) { p[c] = 0.f; q[c] = 0.f; }
        const float4* __restrict__ X8 = (const float4*)g_x8;
        for (int e = beg; e < end; e++) {
            int s = g_col[e];
            float4 v0 = X8[s * 2];
            float4 v1 = X8[s * 2 + 1];
            float ex;
            ex = __expf(v0.x); p[0] += ex; q[0] = fmaf(v0.x, ex, q[0]);
            ex = __expf(v0.y); p[1] += ex; q[1] = fmaf(v0.y, ex, q[1]);
            ex = __expf(v0.z); p[2] += ex; q[2] = fmaf(v0.z, ex, q[2]);
            ex = __expf(v0.w); p[3] += ex; q[3] = fmaf(v0.w, ex, q[3]);
            ex = __expf(v1.x); p[4] += ex; q[4] = fmaf(v1.x, ex, q[4]);
            ex = __expf(v1.y); p[5] += ex; q[5] = fmaf(v1.y, ex, q[5]);
        }
        float o[6];
#pragma unroll
        for (int c = 0; c < 6; c++) o[c] = q[c] / (p[c] + 1e-16f) + x[n * 6 + c];
#pragma unroll
        for (int j = 0; j < 12; j++) {
            float a = b1[j];
#pragma unroll
            for (int c = 0; c < 6; c++) a = fmaf(o[c], w_s[c * 12 + j], a);
            hid[j] = a;
            g_hidden[n * 12 + j] = a;
        }
    }
#pragma unroll
    for (int j = 0; j < 12; j++) {
        float v = hid[j], v2 = v * v;
        for (int off = 16; off; off >>= 1) {
            v += __shfl_down_sync(0xffffffffu, v, off);
            v2 += __shfl_down_sync(0xffffffffu, v2, off);
        }
        if ((t & 31) == 0) { atomicAdd(&sacc[j], v); atomicAdd(&sacc2[j], v2); }
    }
    __syncthreads();
    if (t < 12) {
        g_psum[blockIdx.x * 12 + t] = sacc[t];
        g_psumsq[blockIdx.x * 12 + t] = sacc2[t];
    }
    __threadfence();
    if (t == 0) isLast = (atomicAdd(&g_ctr, 1) == (int)gridDim.x - 1);
    __syncthreads();
    if (isLast) {
        if (t == 0) g_ctr = 0;
        if (t < 12) {
            float s = 0.f, s2 = 0.f;
            for (int i = 0; i < (int)gridDim.x; i++) {
                s += g_psum[i * 12 + t];
                s2 += g_psumsq[i * 12 + t];
            }
            float mu = s / (float)NN;
            float var = fmaxf(s2 / (float)NN - mu * mu, 0.f);
            float sc = gam[t] * rsqrtf(var + 1e-5f);
            g_scale[t] = sc;
            g_shift[t] = bet[t] - mu * sc;
        }
    }
}

// ---------------- layer 0 MLP2: relu(bn(hid12)) @ w2[12,64] + b2 -> h = relu(.) ----------------
__global__ void __launch_bounds__(256) k_l0_mlp2(const float* __restrict__ w2,
                                                 const float* __restrict__ b2) {
    __shared__ float w_s[12 * 64];
    __shared__ float b_s[64];
    int t = threadIdx.x;
    for (int i = t; i < 768; i += 256) w_s[i] = w2[i];
    if (t < 64) b_s[t] = b2[t];
    __syncthreads();
    int n = blockIdx.x * 256 + t;
    if (n >= NN) return;
    float v[12];
#pragma unroll
    for (int j = 0; j < 12; j++)
        v[j] = fmaxf(fmaf(g_hidden[n * 12 + j], g_scale[j], g_shift[j]), 0.f);
    for (int c0 = 0; c0 < 64; c0 += 4) {
        float a0 = b_s[c0], a1 = b_s[c0 + 1], a2 = b_s[c0 + 2], a3 = b_s[c0 + 3];
#pragma unroll
        for (int j = 0; j < 12; j++) {
            float vj = v[j];
            a0 = fmaf(vj, w_s[j * 64 + c0], a0);
            a1 = fmaf(vj, w_s[j * 64 + c0 + 1], a1);
            a2 = fmaf(vj, w_s[j * 64 + c0 + 2], a2);
            a3 = fmaf(vj, w_s[j * 64 + c0 + 3], a3);
        }
        float4 o;
        o.x = fmaxf(a0, 0.f); o.y = fmaxf(a1, 0.f);
        o.z = fmaxf(a2, 0.f); o.w = fmaxf(a3, 0.f);
        *(float4*)(g_h + n * 64 + c0) = o;
    }
}

// ---------------- aggregation, F=64: warp/node, SINGLE PASS (shift-free softmax) ------
// half-warp per edge; each lane owns 4 channels.
__global__ void __launch_bounds__(256) k_agg64() {
    int gt = blockIdx.x * blockDim.x + threadIdx.x;
    int n = gt >> 5;
    if (n >= NN) return;
    int lane = gt & 31;
    int half = lane >> 4, li = lane & 15;
    int beg = g_rowptr[n], end = g_rowptr[n + 1];
    const float4* __restrict__ H = (const float4*)g_h;

    float px = 0.f, py = 0.f, pz = 0.f, pw = 0.f;
    float qx = 0.f, qy = 0.f, qz = 0.f, qw = 0.f;
    int e = beg + half;
    for (; e + 2 < end; e += 4) {
        int i0 = g_col[e], i1 = g_col[e + 2];
        float4 v0 = H[i0 * 16 + li];
        float4 v1 = H[i1 * 16 + li];
        float a, ex;
        a = fmaxf(v0.x, 0.f) + EPS_MSG; ex = __expf(a); px += ex; qx = fmaf(a, ex, qx);
        a = fmaxf(v0.y, 0.f) + EPS_MSG; ex = __expf(a); py += ex; qy = fmaf(a, ex, qy);
        a = fmaxf(v0.z, 0.f) + EPS_MSG; ex = __expf(a); pz += ex; qz = fmaf(a, ex, qz);
        a = fmaxf(v0.w, 0.f) + EPS_MSG; ex = __expf(a); pw += ex; qw = fmaf(a, ex, qw);
        a = fmaxf(v1.x, 0.f) + EPS_MSG; ex = __expf(a); px += ex; qx = fmaf(a, ex, qx);
        a = fmaxf(v1.y, 0.f) + EPS_MSG; ex = __expf(a); py += ex; qy = fmaf(a, ex, qy);
        a = fmaxf(v1.z, 0.f) + EPS_MSG; ex = __expf(a); pz += ex; qz = fmaf(a, ex, qz);
        a = fmaxf(v1.w, 0.f) + EPS_MSG; ex = __expf(a); pw += ex; qw = fmaf(a, ex, qw);
    }
    for (; e < end; e += 2) {
        int i0 = g_col[e];
        float4 v0 = H[i0 * 16 + li];
        float a, ex;
        a = fmaxf(v0.x, 0.f) + EPS_MSG; ex = __expf(a); px += ex; qx = fmaf(a, ex, qx);
        a = fmaxf(v0.y, 0.f) + EPS_MSG; ex = __expf(a); py += ex; qy = fmaf(a, ex, qy);
        a = fmaxf(v0.z, 0.f) + EPS_MSG; ex = __expf(a); pz += ex; qz = fmaf(a, ex, qz);
        a = fmaxf(v0.w, 0.f) + EPS_MSG; ex = __expf(a); pw += ex; qw = fmaf(a, ex, qw);
    }
    px += __shfl_xor_sync(0xffffffffu, px, 16);
    py += __shfl_xor_sync(0xffffffffu, py, 16);
    pz += __shfl_xor_sync(0xffffffffu, pz, 16);
    pw += __shfl_xor_sync(0xffffffffu, pw, 16);
    qx += __shfl_xor_sync(0xffffffffu, qx, 16);
    qy += __shfl_xor_sync(0xffffffffu, qy, 16);
    qz += __shfl_xor_sync(0xffffffffu, qz, 16);
    qw += __shfl_xor_sync(0xffffffffu, qw, 16);

    if (half == 0) {
        float4 r = H[n * 16 + li];
        float4 o;
        o.x = qx / (px + 1e-16f) + fmaxf(r.x, 0.f);
        o.y = qy / (py + 1e-16f) + fmaxf(r.y, 0.f);
        o.z = qz / (pz + 1e-16f) + fmaxf(r.z, 0.f);
        o.w = qw / (pw + 1e-16f) + fmaxf(r.w, 0.f);
        ((float4*)g_out64)[n * 16 + li] = o;
    }
}

// ---------------- GEMM1 (tf32 mma): g_out64[N,64] @ W[64,128] + b -> g_hidden[N,128]
// Fused BN partial stats + last-block finalize.
__global__ void __launch_bounds__(256) k_gemm1(const float* __restrict__ W,
                                               const float* __restrict__ bias,
                                               const float* __restrict__ gam,
                                               const float* __restrict__ bet) {
    __shared__ float a_s[128 * 36];   // [row][k] stride 36
    __shared__ float w_s[32 * 132];   // [k][n] stride 132
    __shared__ int isLast;
    int t = threadIdx.x, lane = t & 31, warp = t >> 5;
    int q = lane & 3, g = lane >> 2;
    int row0 = blockIdx.x * 128;
    int n0w = warp * 16;
    float acc[8][2][4];
#pragma unroll
    for (int i = 0; i < 8; i++)
#pragma unroll
        for (int j = 0; j < 2; j++)
#pragma unroll
            for (int k = 0; k < 4; k++) acc[i][j][k] = 0.f;

    for (int kc = 0; kc < 64; kc += 32) {
#pragma unroll
        for (int i = t; i < 1024; i += 256) {
            int r = i >> 3, kk = (i & 7) << 2;
            int row = row0 + r;
            float4 v = make_float4(0.f, 0.f, 0.f, 0.f);
            if (row < NN) v = *(const float4*)(g_out64 + row * 64 + kc + kk);
            float4 o;
            o.x = f2tf(v.x); o.y = f2tf(v.y); o.z = f2tf(v.z); o.w = f2tf(v.w);
            *(float4*)(a_s + r * 36 + kk) = o;
        }
#pragma unroll
        for (int i = t; i < 1024; i += 256) {
            int kl = i >> 5, n4 = (i & 31) << 2;
            float4 v = *(const float4*)(W + (kc + kl) * 128 + n4);
            float4 o;
            o.x = f2tf(v.x); o.y = f2tf(v.y); o.z = f2tf(v.z); o.w = f2tf(v.w);
            *(float4*)(w_s + kl * 132 + n4) = o;
        }
        __syncthreads();
#pragma unroll
        for (int kk = 0; kk < 32; kk += 8) {
            unsigned b[2][2];
#pragma unroll
            for (int nt = 0; nt < 2; nt++) {
                int n = n0w + nt * 8 + g;
                b[nt][0] = __float_as_uint(w_s[(kk + q) * 132 + n]);
                b[nt][1] = __float_as_uint(w_s[(kk + 4 + q) * 132 + n]);
            }
#pragma unroll
            for (int mt = 0; mt < 8; mt++) {
                int r = mt * 16 + g;
                unsigned a0 = __float_as_uint(a_s[r * 36 + kk + q]);
                unsigned a1 = __float_as_uint(a_s[(r + 8) * 36 + kk + q]);
                unsigned a2 = __float_as_uint(a_s[r * 36 + kk + 4 + q]);
                unsigned a3 = __float_as_uint(a_s[(r + 8) * 36 + kk + 4 + q]);
                mma_tf32(acc[mt][0], a0, a1, a2, a3, b[0][0], b[0][1]);
                mma_tf32(acc[mt][1], a0, a1, a2, a3, b[1][0], b[1][1]);
            }
        }
        __syncthreads();
    }
#pragma unroll
    for (int nt = 0; nt < 2; nt++) {
        int c = n0w + nt * 8 + 2 * q;
        float2 bv = *(const float2*)(bias + c);
        float s0 = 0.f, s1 = 0.f, s20 = 0.f, s21 = 0.f;
#pragma unroll
        for (int mt = 0; mt < 8; mt++) {
            int rA = row0 + mt * 16 + g, rB = rA + 8;
            float v0 = acc[mt][nt][0] + bv.x, v1 = acc[mt][nt][1] + bv.y;
            float v2 = acc[mt][nt][2] + bv.x, v3 = acc[mt][nt][3] + bv.y;
            if (rA < NN) {
                *(float2*)(g_hidden + rA * 128 + c) = make_float2(v0, v1);
                s0 += v0; s20 = fmaf(v0, v0, s20);
                s1 += v1; s21 = fmaf(v1, v1, s21);
            }
            if (rB < NN) {
                *(float2*)(g_hidden + rB * 128 + c) = make_float2(v2, v3);
                s0 += v2; s20 = fmaf(v2, v2, s20);
                s1 += v3; s21 = fmaf(v3, v3, s21);
            }
        }
#pragma unroll
        for (int off = 16; off >= 4; off >>= 1) {
            s0 += __shfl_down_sync(0xffffffffu, s0, off);
            s1 += __shfl_down_sync(0xffffffffu, s1, off);
            s20 += __shfl_down_sync(0xffffffffu, s20, off);
            s21 += __shfl_down_sync(0xffffffffu, s21, off);
        }
        if (lane < 4) {
            int cc = n0w + nt * 8 + 2 * lane;
            g_psum[blockIdx.x * 128 + cc] = s0;
            g_psum[blockIdx.x * 128 + cc + 1] = s1;
            g_psumsq[blockIdx.x * 128 + cc] = s20;
            g_psumsq[blockIdx.x * 128 + cc + 1] = s21;
        }
    }
    __threadfence();
    if (t == 0) isLast = (atomicAdd(&g_ctr, 1) == (int)gridDim.x - 1);
    __syncthreads();
    if (isLast) {
        if (t == 0) g_ctr = 0;
        if (t < 128) {
            float s = 0.f, s2 = 0.f;
            int nb = (int)gridDim.x;
#pragma unroll 4
            for (int i = 0; i < nb; i++) {
                s += g_psum[i * 128 + t];
                s2 += g_psumsq[i * 128 + t];
            }
            float mu = s / (float)NN;
            float var = fmaxf(s2 / (float)NN - mu * mu, 0.f);
            float sc = gam[t] * rsqrtf(var + 1e-5f);
            g_scale[t] = sc;
            g_shift[t] = bet[t] - mu * sc;
        }
    }
}

// ---------------- GEMM2 (tf32 mma): relu(bn(g_hidden))[N,128] @ W[128,64] + b; h += .
__global__ void __launch_bounds__(256) k_gemm2(const float* __restrict__ W,
                                               const float* __restrict__ bias) {
    __shared__ float a_s[128 * 36];   // [row][k] stride 36
    __shared__ float w_s[32 * 68];    // [k][n] stride 68
    int t = threadIdx.x, lane = t & 31, warp = t >> 5;
    int q = lane & 3, g = lane >> 2;
    int row0 = blockIdx.x * 128;
    int n0w = warp * 8;
    float acc[8][4];
#pragma unroll
    for (int i = 0; i < 8; i++)
#pragma unroll
        for (int k = 0; k < 4; k++) acc[i][k] = 0.f;

    for (int kc = 0; kc < 128; kc += 32) {
#pragma unroll
        for (int i = t; i < 1024; i += 256) {
            int r = i >> 3, kk = (i & 7) << 2;
            int row = row0 + r;
            float4 o = make_float4(0.f, 0.f, 0.f, 0.f);
            if (row < NN) {
                float4 hv = *(const float4*)(g_hidden + row * 128 + kc + kk);
                float4 sc = *(const float4*)(g_scale + kc + kk);
                float4 sh = *(const float4*)(g_shift + kc + kk);
                o.x = f2tf(fmaxf(fmaf(hv.x, sc.x, sh.x), 0.f));
                o.y = f2tf(fmaxf(fmaf(hv.y, sc.y, sh.y), 0.f));
                o.z = f2tf(fmaxf(fmaf(hv.z, sc.z, sh.z), 0.f));
                o.w = f2tf(fmaxf(fmaf(hv.w, sc.w, sh.w), 0.f));
            }
            *(float4*)(a_s + r * 36 + kk) = o;
        }
#pragma unroll
        for (int i = t; i < 512; i += 256) {
            int kl = i >> 4, n4 = (i & 15) << 2;
            float4 v = *(const float4*)(W + (kc + kl) * 64 + n4);
            float4 o;
            o.x = f2tf(v.x); o.y = f2tf(v.y); o.z = f2tf(v.z); o.w = f2tf(v.w);
            *(float4*)(w_s + kl * 68 + n4) = o;
        }
        __syncthreads();
#pragma unroll
        for (int kk = 0; kk < 32; kk += 8) {
            int n = n0w + g;
            unsigned b0 = __float_as_uint(w_s[(kk + q) * 68 + n]);
            unsigned b1 = __float_as_uint(w_s[(kk + 4 + q) * 68 + n]);
#pragma unroll
            for (int mt = 0; mt < 8; mt++) {
                int r = mt * 16 + g;
                unsigned a0 = __float_as_uint(a_s[r * 36 + kk + q]);
                unsigned a1 = __float_as_uint(a_s[(r + 8) * 36 + kk + q]);
                unsigned a2 = __float_as_uint(a_s[r * 36 + kk + 4 + q]);
                unsigned a3 = __float_as_uint(a_s[(r + 8) * 36 + kk + 4 + q]);
                mma_tf32(acc[mt], a0, a1, a2, a3, b0, b1);
            }
        }
        __syncthreads();
    }
    int c = n0w + 2 * q;
    float2 bv = *(const float2*)(bias + c);
#pragma unroll
    for (int mt = 0; mt < 8; mt++) {
        int rA = row0 + mt * 16 + g, rB = rA + 8;
        if (rA < NN) {
            float2 hv = *(float2*)(g_h + rA * 64 + c);
            hv.x += acc[mt][0] + bv.x;
            hv.y += acc[mt][1] + bv.y;
            *(float2*)(g_h + rA * 64 + c) = hv;
        }
        if (rB < NN) {
            float2 hv = *(float2*)(g_h + rB * 64 + c);
            hv.x += acc[mt][2] + bv.x;
            hv.y += acc[mt][3] + bv.y;
            *(float2*)(g_h + rB * 64 + c) = hv;
        }
    }
}

// ---------------- pool: run-length max over sorted batch + encoded atomicMax ----------------
__global__ void __launch_bounds__(256) k_pool(const int* __restrict__ batch) {
    int t = threadIdx.x;
    int c = t & 63, sub = t >> 6;
    int n0 = blockIdx.x * 64 + sub * 16;
    float cur = -__int_as_float(0x7f800000);  // -inf
    int curb = -1;
    for (int i = 0; i < 16; i++) {
        int n = n0 + i;
        if (n >= NN) break;
        int b = batch[n];
        if (b != curb) {
            if (curb >= 0) atomicMax(&g_pool[curb * 64 + c], encf(cur));
            curb = b;
            cur = -__int_as_float(0x7f800000);
        }
        cur = fmaxf(cur, g_h[n * 64 + c]);
    }
    if (curb >= 0) atomicMax(&g_pool[curb * 64 + c], encf(cur));
}

// ---------------- final MLP: [64,64] -> relu -> [64,80] ----------------
__global__ void __launch_bounds__(256) k_final(const float* __restrict__ w1,
                                               const float* __restrict__ b1,
                                               const float* __restrict__ w2,
                                               const float* __restrict__ b2,
                                               float* __restrict__ out) {
    __shared__ float g_s[64 * 64];
    __shared__ float t_s[64 * 64];
    int t = threadIdx.x;
    for (int i = t; i < 4096; i += 256) {
        unsigned u = g_pool[i];
        g_s[i] = (u == ENC_NEGINF) ? 0.f : decf(u);
    }
    __syncthreads();
    for (int e = t; e < 4096; e += 256) {
        int r = e >> 6, c = e & 63;
        float a = b1[c];
        for (int k = 0; k < 64; k++) a = fmaf(g_s[r * 64 + k], w1[k * 64 + c], a);
        t_s[e] = fmaxf(a, 0.f);
    }
    __syncthreads();
    for (int e = t; e < 5120; e += 256) {
        int r = e / 80, c = e % 80;
        float a = b2[c];
        for (int k = 0; k < 64; k++) a = fmaf(t_s[r * 64 + k], w2[k * 80 + c], a);
        out[e] = a;
    }
}

// ---------------- launch ----------------
extern "C" void kernel_launch(void* const* d_in, const int* in_sizes, int n_in,
                              void* d_out, int out_size) {
    const float* x    = (const float*)d_in[0];
    const int*   ei   = (const int*)d_in[1];
    const int*   batch = (const int*)d_in[2];
    const float* cw1  = (const float*)d_in[3];
    const float* cb1  = (const float*)d_in[4];
    const float* cg1  = (const float*)d_in[5];
    const float* cbe1 = (const float*)d_in[6];
    const float* cw2  = (const float*)d_in[7];
    const float* cb2  = (const float*)d_in[8];
    const float* Lw1  = (const float*)d_in[9];
    const float* Lb1  = (const float*)d_in[10];
    const float* Lg1  = (const float*)d_in[11];
    const float* Lbe1 = (const float*)d_in[12];
    const float* Lw2  = (const float*)d_in[13];
    const float* Lb2  = (const float*)d_in[14];
    const float* mw1  = (const float*)d_in[15];
    const float* mb1  = (const float*)d_in[16];
    const float* mw2  = (const float*)d_in[17];
    const float* mb2  = (const float*)d_in[18];
    float* out = (float*)d_out;

    const int* src = ei;
    const int* dst = ei + EE;

    // CSR build
    k_init<<<391, 256>>>(x);
    k_deg<<<EE / 256, 256>>>(dst);
    k_scan1<<<98, 1024>>>();
    k_scan2<<<1, 128>>>();
    k_scan3<<<391, 256>>>();
    k_scatter<<<EE / 256, 256>>>(src, dst);

    // layer 0 (6 -> 12 -> 64), h = relu(genconv(x))
    k_l0<<<391, 256>>>(x, cw1, cb1, cg1, cbe1);
    k_l0_mlp2<<<391, 256>>>(cw2, cb2);

    // layers 1..3: h += genconv(relu(h))
    for (int i = 0; i < 3; i++) {
        k_agg64<<<12500, 256>>>();
        k_gemm1<<<782, 256>>>(Lw1 + i * 64 * 128, Lb1 + i * 128,
                              Lg1 + i * 128, Lbe1 + i * 128);
        k_gemm2<<<782, 256>>>(Lw2 + i * 128 * 64, Lb2 + i * 64);
    }

    k_pool<<<1563, 256>>>(batch);
    k_final<<<1, 256>>>(mw1, mb1, mw2, mb2, out);
}